// round 2
// baseline (speedup 1.0000x reference)
#include <cuda_runtime.h>
#include <math.h>
#include <stdint.h>

#define TT 3
#define RR 6
#define HH 4
#define DKK 64
#define DD 256
#define NN 50000
#define EE 400000
#define NPADMAX (NN + TT * 64)

// ---------------- scratch (device globals: sanctioned, no runtime alloc) ----------------
__device__ float g_k[(size_t)NN * DD];
__device__ float g_q[(size_t)NN * DD];
__device__ float g_v[(size_t)NN * DD];
__device__ float g_t[(size_t)NN * DD];
__device__ float g_trans[(size_t)NN * DD];
__device__ float g_krel[(size_t)RR * NN * DD];
__device__ float g_vrel[(size_t)RR * NN * DD];
__device__ float g_ex[(size_t)EE * HH];
__device__ float g_denom[(size_t)NN * RR * HH];
__device__ float g_invnrel[NN];
__device__ int   g_hasmsg[NN];
__device__ int   g_perm[NPADMAX];
__device__ int   g_cnt[TT];
__device__ int   g_cursor[TT];
__device__ int   g_padoff[TT + 1];

// ---------------- type bucketing (counting sort by node type) ----------------
__global__ void count_types(const int* __restrict__ nt, int n) {
    int i = blockIdx.x * blockDim.x + threadIdx.x;
    if (i < n) atomicAdd(&g_cnt[nt[i]], 1);
}

__global__ void make_offsets() {
    if (threadIdx.x == 0 && blockIdx.x == 0) {
        int off = 0;
        for (int t = 0; t < TT; t++) {
            g_padoff[t] = off;
            off += ((g_cnt[t] + 63) >> 6) << 6;
        }
        g_padoff[TT] = off;
    }
}

__global__ void scatter_perm(const int* __restrict__ nt, int n) {
    int i = blockIdx.x * blockDim.x + threadIdx.x;
    if (i < n) {
        int t = nt[i];
        int pos = g_padoff[t] + atomicAdd(&g_cursor[t], 1);
        g_perm[pos] = i;
    }
}

// ---------------- typed linear GEMM: out[n] = (A[n]*scale[n]) @ W[type(n)] + bias[type(n)]
// Rows pre-sorted by type into padded segments -> every 64-row tile is uniform-type.
// BM=64, BN=64, BK=16, 256 threads, 4x4 micro-tile per thread.
struct GemmArgs {
    const float* A;
    const float* scale;     // nullptr -> no scaling
    const float* W[3];
    const float* bias[3];
    float*       out[3];
};

__global__ void typed_gemm(GemmArgs ga) {
    __shared__ float As[16][65];   // [k][row], padded
    __shared__ float Bs[16][64];   // [k][col]
    __shared__ int   s_nodes[64];
    __shared__ float s_scale[64];

    int row0 = blockIdx.x * 64;
    if (row0 >= g_padoff[TT]) return;
    int t = 0;
#pragma unroll
    for (int tt = 0; tt < TT - 1; tt++)
        if (row0 >= g_padoff[tt + 1]) t = tt + 1;

    int tid = threadIdx.x;
    if (tid < 64) {
        int nd = g_perm[row0 + tid];
        s_nodes[tid] = nd;
        s_scale[tid] = (ga.scale != nullptr && nd >= 0) ? ga.scale[nd] : 1.0f;
    }
    __syncthreads();

    int z = blockIdx.z;
    const float* W = ga.W[z] + (size_t)t * DD * DD + blockIdx.y * 64;

    int tx = tid & 15, ty = tid >> 4;
    float acc[4][4];
#pragma unroll
    for (int i = 0; i < 4; i++)
#pragma unroll
        for (int j = 0; j < 4; j++) acc[i][j] = 0.f;

    int lr = tid >> 2;            // A-load row 0..63
    int lc = (tid & 3) << 2;      // A-load col 0/4/8/12
    int nd_l = s_nodes[lr];
    const float* Arow = (nd_l >= 0) ? (ga.A + (size_t)nd_l * DD) : nullptr;
    float sc = s_scale[lr];
    int rb = tid >> 4;            // B-load row 0..15
    int cb = (tid & 15) << 2;     // B-load col

    for (int k0 = 0; k0 < DD; k0 += 16) {
        float4 av = make_float4(0.f, 0.f, 0.f, 0.f);
        if (Arow) {
            av = *(const float4*)(Arow + k0 + lc);
            av.x *= sc; av.y *= sc; av.z *= sc; av.w *= sc;
        }
        As[lc + 0][lr] = av.x;
        As[lc + 1][lr] = av.y;
        As[lc + 2][lr] = av.z;
        As[lc + 3][lr] = av.w;
        *(float4*)&Bs[rb][cb] = *(const float4*)(W + (size_t)(k0 + rb) * DD + cb);
        __syncthreads();
#pragma unroll
        for (int kk = 0; kk < 16; kk++) {
            float a0 = As[kk][ty * 4 + 0];
            float a1 = As[kk][ty * 4 + 1];
            float a2 = As[kk][ty * 4 + 2];
            float a3 = As[kk][ty * 4 + 3];
            float4 b = *(float4*)&Bs[kk][tx * 4];
            acc[0][0] = fmaf(a0, b.x, acc[0][0]); acc[0][1] = fmaf(a0, b.y, acc[0][1]);
            acc[0][2] = fmaf(a0, b.z, acc[0][2]); acc[0][3] = fmaf(a0, b.w, acc[0][3]);
            acc[1][0] = fmaf(a1, b.x, acc[1][0]); acc[1][1] = fmaf(a1, b.y, acc[1][1]);
            acc[1][2] = fmaf(a1, b.z, acc[1][2]); acc[1][3] = fmaf(a1, b.w, acc[1][3]);
            acc[2][0] = fmaf(a2, b.x, acc[2][0]); acc[2][1] = fmaf(a2, b.y, acc[2][1]);
            acc[2][2] = fmaf(a2, b.z, acc[2][2]); acc[2][3] = fmaf(a2, b.w, acc[2][3]);
            acc[3][0] = fmaf(a3, b.x, acc[3][0]); acc[3][1] = fmaf(a3, b.y, acc[3][1]);
            acc[3][2] = fmaf(a3, b.z, acc[3][2]); acc[3][3] = fmaf(a3, b.w, acc[3][3]);
        }
        __syncthreads();
    }

    float4 bv = *(const float4*)(ga.bias[z] + (size_t)t * DD + blockIdx.y * 64 + tx * 4);
    float* out = ga.out[z];
#pragma unroll
    for (int i = 0; i < 4; i++) {
        int nd = s_nodes[ty * 4 + i];
        if (nd >= 0) {
            float* o = out + (size_t)nd * DD + blockIdx.y * 64 + tx * 4;
            o[0] = acc[i][0] + bv.x;
            o[1] = acc[i][1] + bv.y;
            o[2] = acc[i][2] + bv.z;
            o[3] = acc[i][3] + bv.w;
        }
    }
}

// ---------------- relation transforms: krel[r,n,h,:] = k[n,h,:] @ rel_att[r,h]; same for v/msg
// Block = 32 nodes. Thread owns one output column (h,e); A column chunks in registers.
__global__ void rel_transform(const float* __restrict__ Watt,
                              const float* __restrict__ Wmsg,
                              int n) {
    extern __shared__ float sm[];
    float* tile = sm;                 // 32 * 256
    float* Am   = sm + 32 * DD;       // 4 * 64 * 64

    int tid = threadIdx.x;
    int row0 = blockIdx.x * 32;
    int h = tid >> 6, e = tid & 63;

    for (int phase = 0; phase < 2; phase++) {
        const float* src = phase ? g_v : g_k;
        const float* Wp  = phase ? Wmsg : Watt;
        float* dst       = phase ? g_vrel : g_krel;

        __syncthreads();
        for (int i = tid; i < 32 * DD / 4; i += 256) {
            int rrow = i >> 6;
            int cc = (i & 63) << 2;
            float4 val = make_float4(0.f, 0.f, 0.f, 0.f);
            int node = row0 + rrow;
            if (node < n) val = *(const float4*)(src + (size_t)node * DD + cc);
            *(float4*)&tile[rrow * DD + cc] = val;
        }

        for (int r = 0; r < RR; r++) {
            __syncthreads();
            for (int i = tid; i < HH * DKK * DKK / 4; i += 256)
                *(float4*)&Am[i * 4] = *(const float4*)(Wp + (size_t)r * HH * DKK * DKK + i * 4);
            __syncthreads();

            float acc[32];
#pragma unroll
            for (int i = 0; i < 32; i++) acc[i] = 0.f;

            for (int d0 = 0; d0 < DKK; d0 += 16) {
                float areg[16];
#pragma unroll
                for (int dd = 0; dd < 16; dd++)
                    areg[dd] = Am[(h * DKK + d0 + dd) * DKK + e];
#pragma unroll
                for (int i = 0; i < 32; i++) {
                    const float4* kp = (const float4*)&tile[i * DD + h * DKK + d0];
#pragma unroll
                    for (int c4 = 0; c4 < 4; c4++) {
                        float4 kv = kp[c4];
                        acc[i] = fmaf(kv.x, areg[c4 * 4 + 0], acc[i]);
                        acc[i] = fmaf(kv.y, areg[c4 * 4 + 1], acc[i]);
                        acc[i] = fmaf(kv.z, areg[c4 * 4 + 2], acc[i]);
                        acc[i] = fmaf(kv.w, areg[c4 * 4 + 3], acc[i]);
                    }
                }
            }
#pragma unroll
            for (int i = 0; i < 32; i++) {
                int node = row0 + i;
                if (node < n) dst[((size_t)r * n + node) * DD + tid] = acc[i];
            }
        }
    }
}

// ---------------- edge pass 1: att -> exp, segment denom (softmax shift-invariant; max skipped)
__global__ void edge_att(const int* __restrict__ esrc, const int* __restrict__ edst,
                         const int* __restrict__ etype, const float* __restrict__ rel_pri,
                         int ne, int n) {
    int e = blockIdx.x * 8 + (threadIdx.x >> 5);
    if (e >= ne) return;
    int L = threadIdx.x & 31;
    int src = esrc[e], dst = edst[e], r = etype[e];

    const float4* qp = (const float4*)(g_q + (size_t)dst * DD) + L * 2;
    const float4* kp = (const float4*)(g_krel + ((size_t)r * n + src) * DD) + L * 2;
    float4 q0 = qp[0], q1 = qp[1];
    float4 k0 = kp[0], k1 = kp[1];
    float s = q0.x * k0.x + q0.y * k0.y + q0.z * k0.z + q0.w * k0.w
            + q1.x * k1.x + q1.y * k1.y + q1.z * k1.z + q1.w * k1.w;
    s += __shfl_xor_sync(0xffffffffu, s, 1);
    s += __shfl_xor_sync(0xffffffffu, s, 2);
    s += __shfl_xor_sync(0xffffffffu, s, 4);
    if ((L & 7) == 0) {
        int h = L >> 3;
        float att = s * rel_pri[r * HH + h] * 0.125f;   // 1/sqrt(64)
        float ex = expf(att);
        g_ex[(size_t)e * HH + h] = ex;
        atomicAdd(&g_denom[((size_t)dst * RR + r) * HH + h], ex);
    }
}

// ---------------- edge pass 2: t[dst] += w * v_rel[r,src]  (vectorized L2 reductions)
__global__ void edge_aggregate(const int* __restrict__ esrc, const int* __restrict__ edst,
                               const int* __restrict__ etype, int ne, int n) {
    int e = blockIdx.x * 8 + (threadIdx.x >> 5);
    if (e >= ne) return;
    int L = threadIdx.x & 31;
    int src = esrc[e], dst = edst[e], r = etype[e];
    int h = L >> 3;
    float w = g_ex[(size_t)e * HH + h] / g_denom[((size_t)dst * RR + r) * HH + h];

    const float4* vp = (const float4*)(g_vrel + ((size_t)r * n + src) * DD) + L * 2;
    float4 v0 = vp[0], v1 = vp[1];
    float* tp = g_t + (size_t)dst * DD + L * 8;
    asm volatile("red.global.add.v4.f32 [%0], {%1,%2,%3,%4};"
                 :: "l"(tp), "f"(v0.x * w), "f"(v0.y * w), "f"(v0.z * w), "f"(v0.w * w)
                 : "memory");
    asm volatile("red.global.add.v4.f32 [%0], {%1,%2,%3,%4};"
                 :: "l"(tp + 4), "f"(v1.x * w), "f"(v1.y * w), "f"(v1.z * w), "f"(v1.w * w)
                 : "memory");
}

// ---------------- per-node: relation count -> 1/nrel, has_msg
__global__ void node_nrel(int n) {
    int i = blockIdx.x * blockDim.x + threadIdx.x;
    if (i >= n) return;
    int c = 0;
#pragma unroll
    for (int r = 0; r < RR; r++)
        c += (g_denom[((size_t)i * RR + r) * HH] > 0.f) ? 1 : 0;
    g_hasmsg[i] = (c > 0) ? 1 : 0;
    g_invnrel[i] = 1.0f / (float)(c > 0 ? c : 1);
}

// ---------------- final: gated residual + layernorm + no-message passthrough (warp per node)
__global__ void finalize(const float* __restrict__ x, const float* __restrict__ skip,
                         const float* __restrict__ ln_g, const float* __restrict__ ln_b,
                         const int* __restrict__ nt, float* __restrict__ out, int n) {
    int node = blockIdx.x * 8 + (threadIdx.x >> 5);
    if (node >= n) return;
    int L = threadIdx.x & 31;
    int t = nt[node];
    float alpha = 1.0f / (1.0f + expf(-skip[t]));
    float beta = 1.0f - alpha;

    const float4* xp = (const float4*)(x + (size_t)node * DD) + L * 2;
    const float4* tp = (const float4*)(g_trans + (size_t)node * DD) + L * 2;
    float4 x0 = xp[0], x1 = xp[1];
    float4 t0 = tp[0], t1 = tp[1];

    float o[8];
    o[0] = t0.x * alpha + x0.x * beta;
    o[1] = t0.y * alpha + x0.y * beta;
    o[2] = t0.z * alpha + x0.z * beta;
    o[3] = t0.w * alpha + x0.w * beta;
    o[4] = t1.x * alpha + x1.x * beta;
    o[5] = t1.y * alpha + x1.y * beta;
    o[6] = t1.z * alpha + x1.z * beta;
    o[7] = t1.w * alpha + x1.w * beta;

    float s = 0.f, s2 = 0.f;
#pragma unroll
    for (int j = 0; j < 8; j++) { s += o[j]; s2 += o[j] * o[j]; }
#pragma unroll
    for (int off = 16; off > 0; off >>= 1) {
        s  += __shfl_xor_sync(0xffffffffu, s, off);
        s2 += __shfl_xor_sync(0xffffffffu, s2, off);
    }
    float mu = s * (1.0f / DD);
    float var = s2 * (1.0f / DD) - mu * mu;
    float rstd = rsqrtf(var + 1e-5f);

    float4 r0, r1;
    if (g_hasmsg[node]) {
        const float4* gp = (const float4*)(ln_g + (size_t)t * DD) + L * 2;
        const float4* bp = (const float4*)(ln_b + (size_t)t * DD) + L * 2;
        float4 g0 = gp[0], g1 = gp[1];
        float4 b0 = bp[0], b1 = bp[1];
        r0.x = (o[0] - mu) * rstd * g0.x + b0.x;
        r0.y = (o[1] - mu) * rstd * g0.y + b0.y;
        r0.z = (o[2] - mu) * rstd * g0.z + b0.z;
        r0.w = (o[3] - mu) * rstd * g0.w + b0.w;
        r1.x = (o[4] - mu) * rstd * g1.x + b1.x;
        r1.y = (o[5] - mu) * rstd * g1.y + b1.y;
        r1.z = (o[6] - mu) * rstd * g1.z + b1.z;
        r1.w = (o[7] - mu) * rstd * g1.w + b1.w;
    } else {
        r0 = x0; r1 = x1;
    }
    float4* op = (float4*)(out + (size_t)node * DD) + L * 2;
    op[0] = r0;
    op[1] = r1;
}

// ---------------- host launcher ----------------
extern "C" void kernel_launch(void* const* d_in, const int* in_sizes, int n_in,
                              void* d_out, int out_size) {
    const float* x       = (const float*)d_in[0];
    const float* Wk      = (const float*)d_in[1];
    const float* bk      = (const float*)d_in[2];
    const float* Wq      = (const float*)d_in[3];
    const float* bq      = (const float*)d_in[4];
    const float* Wv      = (const float*)d_in[5];
    const float* bv      = (const float*)d_in[6];
    const float* Wa      = (const float*)d_in[7];
    const float* ba      = (const float*)d_in[8];
    const float* rel_pri = (const float*)d_in[9];
    const float* rel_att = (const float*)d_in[10];
    const float* rel_msg = (const float*)d_in[11];
    const float* skip    = (const float*)d_in[12];
    const float* ln_g    = (const float*)d_in[13];
    const float* ln_b    = (const float*)d_in[14];
    const int* node_type = (const int*)d_in[15];
    const int* edge_src  = (const int*)d_in[16];
    const int* edge_dst  = (const int*)d_in[17];
    const int* edge_type = (const int*)d_in[18];

    int n  = in_sizes[0] / DD;
    int ne = in_sizes[16];
    if (n > NN || ne > EE) return;  // sized for the benchmark shapes

    void *p_cnt, *p_cursor, *p_perm, *p_denom, *p_t;
    void *p_k, *p_q, *p_v, *p_trans, *p_invnrel;
    cudaGetSymbolAddress(&p_cnt, g_cnt);
    cudaGetSymbolAddress(&p_cursor, g_cursor);
    cudaGetSymbolAddress(&p_perm, g_perm);
    cudaGetSymbolAddress(&p_denom, g_denom);
    cudaGetSymbolAddress(&p_t, g_t);
    cudaGetSymbolAddress(&p_k, g_k);
    cudaGetSymbolAddress(&p_q, g_q);
    cudaGetSymbolAddress(&p_v, g_v);
    cudaGetSymbolAddress(&p_trans, g_trans);
    cudaGetSymbolAddress(&p_invnrel, g_invnrel);

    cudaMemsetAsync(p_cnt, 0, sizeof(int) * TT);
    cudaMemsetAsync(p_cursor, 0, sizeof(int) * TT);
    cudaMemsetAsync(p_perm, 0xFF, sizeof(int) * NPADMAX);
    cudaMemsetAsync(p_denom, 0, sizeof(float) * (size_t)n * RR * HH);
    cudaMemsetAsync(p_t, 0, sizeof(float) * (size_t)n * DD);

    // type bucketing
    count_types<<<(n + 255) / 256, 256>>>(node_type, n);
    make_offsets<<<1, 1>>>();
    scatter_perm<<<(n + 255) / 256, 256>>>(node_type, n);

    // fused KQV typed linears (grid.z = {k,q,v})
    GemmArgs g1;
    g1.A = x; g1.scale = nullptr;
    g1.W[0] = Wk; g1.W[1] = Wq; g1.W[2] = Wv;
    g1.bias[0] = bk; g1.bias[1] = bq; g1.bias[2] = bv;
    g1.out[0] = (float*)p_k; g1.out[1] = (float*)p_q; g1.out[2] = (float*)p_v;
    dim3 grid1((n + 63) / 64 + TT, DD / 64, 3);
    typed_gemm<<<grid1, 256>>>(g1);

    // relation transforms (96KB dynamic smem)
    cudaFuncSetAttribute(rel_transform, cudaFuncAttributeMaxDynamicSharedMemorySize, 96 * 1024);
    rel_transform<<<(n + 31) / 32, 256, 96 * 1024>>>(rel_att, rel_msg, n);

    // edge passes
    edge_att<<<(ne + 7) / 8, 256>>>(edge_src, edge_dst, edge_type, rel_pri, ne, n);
    edge_aggregate<<<(ne + 7) / 8, 256>>>(edge_src, edge_dst, edge_type, ne, n);
    node_nrel<<<(n + 255) / 256, 256>>>(n);

    // output typed linear (with 1/nrel row scaling)
    GemmArgs g2;
    g2.A = (const float*)p_t; g2.scale = (const float*)p_invnrel;
    g2.W[0] = Wa; g2.W[1] = Wa; g2.W[2] = Wa;
    g2.bias[0] = ba; g2.bias[1] = ba; g2.bias[2] = ba;
    g2.out[0] = (float*)p_trans; g2.out[1] = (float*)p_trans; g2.out[2] = (float*)p_trans;
    dim3 grid2((n + 63) / 64 + TT, DD / 64, 1);
    typed_gemm<<<grid2, 256>>>(g2);

    // gated residual + LN + passthrough
    finalize<<<(n + 7) / 8, 256>>>(x, skip, ln_g, ln_b, node_type, (float*)d_out, n);
}

// round 3
// speedup vs baseline: 1.0022x; 1.0022x over previous
#include <cuda_runtime.h>
#include <math.h>
#include <stdint.h>

#define TT 3
#define RR 6
#define HH 4
#define DKK 64
#define DD 256
#define NN 50000
#define EE 400000
#define NPADMAX (NN + TT * 64)

// ---------------- scratch (device globals: sanctioned, no runtime alloc) ----------------
__device__ float g_k[(size_t)NN * DD];
__device__ float g_q[(size_t)NN * DD];
__device__ float g_v[(size_t)NN * DD];
__device__ float g_t[(size_t)NN * DD];
__device__ float g_trans[(size_t)NN * DD];
__device__ float g_krel[(size_t)RR * NN * DD];
__device__ float g_vrel[(size_t)RR * NN * DD];
__device__ float g_ex[(size_t)EE * HH];
__device__ float g_denom[(size_t)NN * RR * HH];
__device__ float g_invnrel[NN];
__device__ int   g_hasmsg[NN];
__device__ int   g_perm[NPADMAX];
__device__ int   g_cnt[TT];
__device__ int   g_cursor[TT];
__device__ int   g_padoff[TT + 1];

// ---------------- type bucketing (counting sort by node type) ----------------
__global__ void count_types(const int* __restrict__ nt, int n) {
    int i = blockIdx.x * blockDim.x + threadIdx.x;
    if (i < n) atomicAdd(&g_cnt[nt[i]], 1);
}

__global__ void make_offsets() {
    if (threadIdx.x == 0 && blockIdx.x == 0) {
        int off = 0;
        for (int t = 0; t < TT; t++) {
            g_padoff[t] = off;
            off += ((g_cnt[t] + 63) >> 6) << 6;
        }
        g_padoff[TT] = off;
    }
}

__global__ void scatter_perm(const int* __restrict__ nt, int n) {
    int i = blockIdx.x * blockDim.x + threadIdx.x;
    if (i < n) {
        int t = nt[i];
        int pos = g_padoff[t] + atomicAdd(&g_cursor[t], 1);
        g_perm[pos] = i;
    }
}

// ---------------- typed linear GEMM: out[n] = (A[n]*scale[n]) @ W[type(n)] + bias[type(n)]
// Rows pre-sorted by type into padded segments -> every 64-row tile is uniform-type.
// BM=64, BN=64, BK=16, 256 threads, 4x4 micro-tile per thread.
struct GemmArgs {
    const float* A;
    const float* scale;     // nullptr -> no scaling
    const float* W[3];
    const float* bias[3];
    float*       out[3];
};

__global__ void typed_gemm(GemmArgs ga) {
    __shared__ float As[16][65];   // [k][row], padded
    __shared__ float Bs[16][64];   // [k][col]
    __shared__ int   s_nodes[64];
    __shared__ float s_scale[64];

    int row0 = blockIdx.x * 64;
    if (row0 >= g_padoff[TT]) return;
    int t = 0;
#pragma unroll
    for (int tt = 0; tt < TT - 1; tt++)
        if (row0 >= g_padoff[tt + 1]) t = tt + 1;

    int tid = threadIdx.x;
    if (tid < 64) {
        int nd = g_perm[row0 + tid];
        s_nodes[tid] = nd;
        s_scale[tid] = (ga.scale != nullptr && nd >= 0) ? ga.scale[nd] : 1.0f;
    }
    __syncthreads();

    int z = blockIdx.z;
    const float* W = ga.W[z] + (size_t)t * DD * DD + blockIdx.y * 64;

    int tx = tid & 15, ty = tid >> 4;
    float acc[4][4];
#pragma unroll
    for (int i = 0; i < 4; i++)
#pragma unroll
        for (int j = 0; j < 4; j++) acc[i][j] = 0.f;

    int lr = tid >> 2;            // A-load row 0..63
    int lc = (tid & 3) << 2;      // A-load col 0/4/8/12
    int nd_l = s_nodes[lr];
    const float* Arow = (nd_l >= 0) ? (ga.A + (size_t)nd_l * DD) : nullptr;
    float sc = s_scale[lr];
    int rb = tid >> 4;            // B-load row 0..15
    int cb = (tid & 15) << 2;     // B-load col

    for (int k0 = 0; k0 < DD; k0 += 16) {
        float4 av = make_float4(0.f, 0.f, 0.f, 0.f);
        if (Arow) {
            av = *(const float4*)(Arow + k0 + lc);
            av.x *= sc; av.y *= sc; av.z *= sc; av.w *= sc;
        }
        As[lc + 0][lr] = av.x;
        As[lc + 1][lr] = av.y;
        As[lc + 2][lr] = av.z;
        As[lc + 3][lr] = av.w;
        *(float4*)&Bs[rb][cb] = *(const float4*)(W + (size_t)(k0 + rb) * DD + cb);
        __syncthreads();
#pragma unroll
        for (int kk = 0; kk < 16; kk++) {
            float a0 = As[kk][ty * 4 + 0];
            float a1 = As[kk][ty * 4 + 1];
            float a2 = As[kk][ty * 4 + 2];
            float a3 = As[kk][ty * 4 + 3];
            float4 b = *(float4*)&Bs[kk][tx * 4];
            acc[0][0] = fmaf(a0, b.x, acc[0][0]); acc[0][1] = fmaf(a0, b.y, acc[0][1]);
            acc[0][2] = fmaf(a0, b.z, acc[0][2]); acc[0][3] = fmaf(a0, b.w, acc[0][3]);
            acc[1][0] = fmaf(a1, b.x, acc[1][0]); acc[1][1] = fmaf(a1, b.y, acc[1][1]);
            acc[1][2] = fmaf(a1, b.z, acc[1][2]); acc[1][3] = fmaf(a1, b.w, acc[1][3]);
            acc[2][0] = fmaf(a2, b.x, acc[2][0]); acc[2][1] = fmaf(a2, b.y, acc[2][1]);
            acc[2][2] = fmaf(a2, b.z, acc[2][2]); acc[2][3] = fmaf(a2, b.w, acc[2][3]);
            acc[3][0] = fmaf(a3, b.x, acc[3][0]); acc[3][1] = fmaf(a3, b.y, acc[3][1]);
            acc[3][2] = fmaf(a3, b.z, acc[3][2]); acc[3][3] = fmaf(a3, b.w, acc[3][3]);
        }
        __syncthreads();
    }

    float4 bv = *(const float4*)(ga.bias[z] + (size_t)t * DD + blockIdx.y * 64 + tx * 4);
    float* out = ga.out[z];
#pragma unroll
    for (int i = 0; i < 4; i++) {
        int nd = s_nodes[ty * 4 + i];
        if (nd >= 0) {
            float* o = out + (size_t)nd * DD + blockIdx.y * 64 + tx * 4;
            o[0] = acc[i][0] + bv.x;
            o[1] = acc[i][1] + bv.y;
            o[2] = acc[i][2] + bv.z;
            o[3] = acc[i][3] + bv.w;
        }
    }
}

// ---------------- relation transforms: krel[r,n,h,:] = k[n,h,:] @ rel_att[r,h]; same for v/msg
// Block = 32 nodes. Thread owns one output column (h,e); A column chunks in registers.
__global__ void rel_transform(const float* __restrict__ Watt,
                              const float* __restrict__ Wmsg,
                              int n) {
    extern __shared__ float sm[];
    float* tile = sm;                 // 32 * 256
    float* Am   = sm + 32 * DD;       // 4 * 64 * 64

    int tid = threadIdx.x;
    int row0 = blockIdx.x * 32;
    int h = tid >> 6, e = tid & 63;

    for (int phase = 0; phase < 2; phase++) {
        const float* src = phase ? g_v : g_k;
        const float* Wp  = phase ? Wmsg : Watt;
        float* dst       = phase ? g_vrel : g_krel;

        __syncthreads();
        for (int i = tid; i < 32 * DD / 4; i += 256) {
            int rrow = i >> 6;
            int cc = (i & 63) << 2;
            float4 val = make_float4(0.f, 0.f, 0.f, 0.f);
            int node = row0 + rrow;
            if (node < n) val = *(const float4*)(src + (size_t)node * DD + cc);
            *(float4*)&tile[rrow * DD + cc] = val;
        }

        for (int r = 0; r < RR; r++) {
            __syncthreads();
            for (int i = tid; i < HH * DKK * DKK / 4; i += 256)
                *(float4*)&Am[i * 4] = *(const float4*)(Wp + (size_t)r * HH * DKK * DKK + i * 4);
            __syncthreads();

            float acc[32];
#pragma unroll
            for (int i = 0; i < 32; i++) acc[i] = 0.f;

            for (int d0 = 0; d0 < DKK; d0 += 16) {
                float areg[16];
#pragma unroll
                for (int dd = 0; dd < 16; dd++)
                    areg[dd] = Am[(h * DKK + d0 + dd) * DKK + e];
#pragma unroll
                for (int i = 0; i < 32; i++) {
                    const float4* kp = (const float4*)&tile[i * DD + h * DKK + d0];
#pragma unroll
                    for (int c4 = 0; c4 < 4; c4++) {
                        float4 kv = kp[c4];
                        acc[i] = fmaf(kv.x, areg[c4 * 4 + 0], acc[i]);
                        acc[i] = fmaf(kv.y, areg[c4 * 4 + 1], acc[i]);
                        acc[i] = fmaf(kv.z, areg[c4 * 4 + 2], acc[i]);
                        acc[i] = fmaf(kv.w, areg[c4 * 4 + 3], acc[i]);
                    }
                }
            }
#pragma unroll
            for (int i = 0; i < 32; i++) {
                int node = row0 + i;
                if (node < n) dst[((size_t)r * n + node) * DD + tid] = acc[i];
            }
        }
    }
}

// ---------------- edge pass 1: att -> exp, segment denom (softmax shift-invariant; max skipped)
__global__ void edge_att(const int* __restrict__ esrc, const int* __restrict__ edst,
                         const int* __restrict__ etype, const float* __restrict__ rel_pri,
                         int ne, int n) {
    int e = blockIdx.x * 8 + (threadIdx.x >> 5);
    if (e >= ne) return;
    int L = threadIdx.x & 31;
    int src = esrc[e], dst = edst[e], r = etype[e];

    const float4* qp = (const float4*)(g_q + (size_t)dst * DD) + L * 2;
    const float4* kp = (const float4*)(g_krel + ((size_t)r * n + src) * DD) + L * 2;
    float4 q0 = qp[0], q1 = qp[1];
    float4 k0 = kp[0], k1 = kp[1];
    float s = q0.x * k0.x + q0.y * k0.y + q0.z * k0.z + q0.w * k0.w
            + q1.x * k1.x + q1.y * k1.y + q1.z * k1.z + q1.w * k1.w;
    s += __shfl_xor_sync(0xffffffffu, s, 1);
    s += __shfl_xor_sync(0xffffffffu, s, 2);
    s += __shfl_xor_sync(0xffffffffu, s, 4);
    if ((L & 7) == 0) {
        int h = L >> 3;
        float att = s * rel_pri[r * HH + h] * 0.125f;   // 1/sqrt(64)
        float ex = expf(att);
        g_ex[(size_t)e * HH + h] = ex;
        atomicAdd(&g_denom[((size_t)dst * RR + r) * HH + h], ex);
    }
}

// ---------------- edge pass 2: t[dst] += w * v_rel[r,src]  (vectorized L2 reductions)
__global__ void edge_aggregate(const int* __restrict__ esrc, const int* __restrict__ edst,
                               const int* __restrict__ etype, int ne, int n) {
    int e = blockIdx.x * 8 + (threadIdx.x >> 5);
    if (e >= ne) return;
    int L = threadIdx.x & 31;
    int src = esrc[e], dst = edst[e], r = etype[e];
    int h = L >> 3;
    float w = g_ex[(size_t)e * HH + h] / g_denom[((size_t)dst * RR + r) * HH + h];

    const float4* vp = (const float4*)(g_vrel + ((size_t)r * n + src) * DD) + L * 2;
    float4 v0 = vp[0], v1 = vp[1];
    float* tp = g_t + (size_t)dst * DD + L * 8;
    asm volatile("red.global.add.v4.f32 [%0], {%1,%2,%3,%4};"
                 :: "l"(tp), "f"(v0.x * w), "f"(v0.y * w), "f"(v0.z * w), "f"(v0.w * w)
                 : "memory");
    asm volatile("red.global.add.v4.f32 [%0], {%1,%2,%3,%4};"
                 :: "l"(tp + 4), "f"(v1.x * w), "f"(v1.y * w), "f"(v1.z * w), "f"(v1.w * w)
                 : "memory");
}

// ---------------- per-node: relation count -> 1/nrel, has_msg
__global__ void node_nrel(int n) {
    int i = blockIdx.x * blockDim.x + threadIdx.x;
    if (i >= n) return;
    int c = 0;
#pragma unroll
    for (int r = 0; r < RR; r++)
        c += (g_denom[((size_t)i * RR + r) * HH] > 0.f) ? 1 : 0;
    g_hasmsg[i] = (c > 0) ? 1 : 0;
    g_invnrel[i] = 1.0f / (float)(c > 0 ? c : 1);
}

// ---------------- final: gated residual + layernorm + no-message passthrough (warp per node)
__global__ void finalize(const float* __restrict__ x, const float* __restrict__ skip,
                         const float* __restrict__ ln_g, const float* __restrict__ ln_b,
                         const int* __restrict__ nt, float* __restrict__ out, int n) {
    int node = blockIdx.x * 8 + (threadIdx.x >> 5);
    if (node >= n) return;
    int L = threadIdx.x & 31;
    int t = nt[node];
    float alpha = 1.0f / (1.0f + expf(-skip[t]));
    float beta = 1.0f - alpha;

    const float4* xp = (const float4*)(x + (size_t)node * DD) + L * 2;
    const float4* tp = (const float4*)(g_trans + (size_t)node * DD) + L * 2;
    float4 x0 = xp[0], x1 = xp[1];
    float4 t0 = tp[0], t1 = tp[1];

    float o[8];
    o[0] = t0.x * alpha + x0.x * beta;
    o[1] = t0.y * alpha + x0.y * beta;
    o[2] = t0.z * alpha + x0.z * beta;
    o[3] = t0.w * alpha + x0.w * beta;
    o[4] = t1.x * alpha + x1.x * beta;
    o[5] = t1.y * alpha + x1.y * beta;
    o[6] = t1.z * alpha + x1.z * beta;
    o[7] = t1.w * alpha + x1.w * beta;

    float s = 0.f, s2 = 0.f;
#pragma unroll
    for (int j = 0; j < 8; j++) { s += o[j]; s2 += o[j] * o[j]; }
#pragma unroll
    for (int off = 16; off > 0; off >>= 1) {
        s  += __shfl_xor_sync(0xffffffffu, s, off);
        s2 += __shfl_xor_sync(0xffffffffu, s2, off);
    }
    float mu = s * (1.0f / DD);
    float var = s2 * (1.0f / DD) - mu * mu;
    float rstd = rsqrtf(var + 1e-5f);

    float4 r0, r1;
    if (g_hasmsg[node]) {
        const float4* gp = (const float4*)(ln_g + (size_t)t * DD) + L * 2;
        const float4* bp = (const float4*)(ln_b + (size_t)t * DD) + L * 2;
        float4 g0 = gp[0], g1 = gp[1];
        float4 b0 = bp[0], b1 = bp[1];
        r0.x = (o[0] - mu) * rstd * g0.x + b0.x;
        r0.y = (o[1] - mu) * rstd * g0.y + b0.y;
        r0.z = (o[2] - mu) * rstd * g0.z + b0.z;
        r0.w = (o[3] - mu) * rstd * g0.w + b0.w;
        r1.x = (o[4] - mu) * rstd * g1.x + b1.x;
        r1.y = (o[5] - mu) * rstd * g1.y + b1.y;
        r1.z = (o[6] - mu) * rstd * g1.z + b1.z;
        r1.w = (o[7] - mu) * rstd * g1.w + b1.w;
    } else {
        r0 = x0; r1 = x1;
    }
    float4* op = (float4*)(out + (size_t)node * DD) + L * 2;
    op[0] = r0;
    op[1] = r1;
}

// ---------------- host launcher ----------------
extern "C" void kernel_launch(void* const* d_in, const int* in_sizes, int n_in,
                              void* d_out, int out_size) {
    const float* x       = (const float*)d_in[0];
    const float* Wk      = (const float*)d_in[1];
    const float* bk      = (const float*)d_in[2];
    const float* Wq      = (const float*)d_in[3];
    const float* bq      = (const float*)d_in[4];
    const float* Wv      = (const float*)d_in[5];
    const float* bv      = (const float*)d_in[6];
    const float* Wa      = (const float*)d_in[7];
    const float* ba      = (const float*)d_in[8];
    const float* rel_pri = (const float*)d_in[9];
    const float* rel_att = (const float*)d_in[10];
    const float* rel_msg = (const float*)d_in[11];
    const float* skip    = (const float*)d_in[12];
    const float* ln_g    = (const float*)d_in[13];
    const float* ln_b    = (const float*)d_in[14];
    const int* node_type = (const int*)d_in[15];
    const int* edge_src  = (const int*)d_in[16];
    const int* edge_dst  = (const int*)d_in[17];
    const int* edge_type = (const int*)d_in[18];

    int n  = in_sizes[0] / DD;
    int ne = in_sizes[16];
    if (n > NN || ne > EE) return;  // sized for the benchmark shapes

    void *p_cnt, *p_cursor, *p_perm, *p_denom, *p_t;
    void *p_k, *p_q, *p_v, *p_trans, *p_invnrel;
    cudaGetSymbolAddress(&p_cnt, g_cnt);
    cudaGetSymbolAddress(&p_cursor, g_cursor);
    cudaGetSymbolAddress(&p_perm, g_perm);
    cudaGetSymbolAddress(&p_denom, g_denom);
    cudaGetSymbolAddress(&p_t, g_t);
    cudaGetSymbolAddress(&p_k, g_k);
    cudaGetSymbolAddress(&p_q, g_q);
    cudaGetSymbolAddress(&p_v, g_v);
    cudaGetSymbolAddress(&p_trans, g_trans);
    cudaGetSymbolAddress(&p_invnrel, g_invnrel);

    cudaMemsetAsync(p_cnt, 0, sizeof(int) * TT);
    cudaMemsetAsync(p_cursor, 0, sizeof(int) * TT);
    cudaMemsetAsync(p_perm, 0xFF, sizeof(int) * NPADMAX);
    cudaMemsetAsync(p_denom, 0, sizeof(float) * (size_t)n * RR * HH);
    cudaMemsetAsync(p_t, 0, sizeof(float) * (size_t)n * DD);

    // type bucketing
    count_types<<<(n + 255) / 256, 256>>>(node_type, n);
    make_offsets<<<1, 1>>>();
    scatter_perm<<<(n + 255) / 256, 256>>>(node_type, n);

    // fused KQV typed linears (grid.z = {k,q,v})
    GemmArgs g1;
    g1.A = x; g1.scale = nullptr;
    g1.W[0] = Wk; g1.W[1] = Wq; g1.W[2] = Wv;
    g1.bias[0] = bk; g1.bias[1] = bq; g1.bias[2] = bv;
    g1.out[0] = (float*)p_k; g1.out[1] = (float*)p_q; g1.out[2] = (float*)p_v;
    dim3 grid1((n + 63) / 64 + TT, DD / 64, 3);
    typed_gemm<<<grid1, 256>>>(g1);

    // relation transforms (96KB dynamic smem)
    cudaFuncSetAttribute(rel_transform, cudaFuncAttributeMaxDynamicSharedMemorySize, 96 * 1024);
    rel_transform<<<(n + 31) / 32, 256, 96 * 1024>>>(rel_att, rel_msg, n);

    // edge passes
    edge_att<<<(ne + 7) / 8, 256>>>(edge_src, edge_dst, edge_type, rel_pri, ne, n);
    edge_aggregate<<<(ne + 7) / 8, 256>>>(edge_src, edge_dst, edge_type, ne, n);
    node_nrel<<<(n + 255) / 256, 256>>>(n);

    // output typed linear (with 1/nrel row scaling)
    GemmArgs g2;
    g2.A = (const float*)p_t; g2.scale = (const float*)p_invnrel;
    g2.W[0] = Wa; g2.W[1] = Wa; g2.W[2] = Wa;
    g2.bias[0] = ba; g2.bias[1] = ba; g2.bias[2] = ba;
    g2.out[0] = (float*)p_trans; g2.out[1] = (float*)p_trans; g2.out[2] = (float*)p_trans;
    dim3 grid2((n + 63) / 64 + TT, DD / 64, 1);
    typed_gemm<<<grid2, 256>>>(g2);

    // gated residual + LN + passthrough
    finalize<<<(n + 7) / 8, 256>>>(x, skip, ln_g, ln_b, node_type, (float*)d_out, n);
}

// round 4
// speedup vs baseline: 1.3333x; 1.3303x over previous
#include <cuda_runtime.h>
#include <math.h>
#include <stdint.h>

#define TT 3
#define RR 6
#define HH 4
#define DKK 64
#define DD 256
#define NN 50000
#define EE 400000
#define NPADMAX (NN + TT * 128)

// ---------------- scratch (device globals: sanctioned, no runtime alloc) ----------------
__device__ float g_k[(size_t)NN * DD];
__device__ float g_q[(size_t)NN * DD];
__device__ float g_v[(size_t)NN * DD];
__device__ float g_t[(size_t)NN * DD];
__device__ float g_trans[(size_t)NN * DD];
__device__ float g_krel[(size_t)RR * NN * DD];
__device__ float g_vrel[(size_t)RR * NN * DD];
__device__ float g_ex[(size_t)EE * HH];
__device__ float g_denom[(size_t)NN * RR * HH];
__device__ float g_invnrel[NN];
__device__ int   g_hasmsg[NN];
__device__ int   g_perm[NPADMAX];
__device__ int   g_cnt[TT];
__device__ int   g_cursor[TT];
__device__ int   g_padoff[TT + 1];

// ---------------- type bucketing (counting sort by node type, 128-padded segments) --------
__global__ void count_types(const int* __restrict__ nt, int n) {
    int i = blockIdx.x * blockDim.x + threadIdx.x;
    if (i < n) atomicAdd(&g_cnt[nt[i]], 1);
}

__global__ void make_offsets() {
    if (threadIdx.x == 0 && blockIdx.x == 0) {
        int off = 0;
        for (int t = 0; t < TT; t++) {
            g_padoff[t] = off;
            off += ((g_cnt[t] + 127) >> 7) << 7;
        }
        g_padoff[TT] = off;
    }
}

__global__ void scatter_perm(const int* __restrict__ nt, int n) {
    int i = blockIdx.x * blockDim.x + threadIdx.x;
    if (i < n) {
        int t = nt[i];
        int pos = g_padoff[t] + atomicAdd(&g_cursor[t], 1);
        g_perm[pos] = i;
    }
}

// ---------------- typed linear GEMM: out[n] = (A[n]*scale[n]) @ W[type(n)] + bias[type(n)]
// BM=128, BN=128, BK=16, 256 threads, 8x8 micro-tile with split fragments (1 B smem / FMA).
struct GemmArgs {
    const float* A;
    const float* scale;     // nullptr -> no scaling
    const float* W[3];
    const float* bias[3];
    float*       out[3];
};

__global__ __launch_bounds__(256) void typed_gemm(GemmArgs ga) {
    __shared__ float As[16][132];   // [k][row], stride 132 floats = 528B (16B aligned)
    __shared__ float Bs[16][128];   // [k][col]
    __shared__ int   s_nodes[128];
    __shared__ float s_scale[128];

    int row0 = blockIdx.x * 128;
    if (row0 >= g_padoff[TT]) return;
    int t = 0;
#pragma unroll
    for (int tt = 0; tt < TT - 1; tt++)
        if (row0 >= g_padoff[tt + 1]) t = tt + 1;

    int tid = threadIdx.x;
    if (tid < 128) {
        int nd = g_perm[row0 + tid];
        s_nodes[tid] = nd;
        s_scale[tid] = (ga.scale != nullptr && nd >= 0) ? ga.scale[nd] : 1.0f;
    }
    __syncthreads();

    int z = blockIdx.z;
    const float* W = ga.W[z] + (size_t)t * DD * DD + blockIdx.y * 128;

    int tx = tid & 15, ty = tid >> 4;
    float acc[8][8];
#pragma unroll
    for (int i = 0; i < 8; i++)
#pragma unroll
        for (int j = 0; j < 8; j++) acc[i][j] = 0.f;

    // A loader: lr = tid&127 (32 distinct rows per warp -> conflict-free transpose STS)
    int lr = tid & 127;
    int lc = (tid >> 7) * 8;        // 0 or 8
    int nd_l = s_nodes[lr];
    const float* Arow = (nd_l >= 0) ? (ga.A + (size_t)nd_l * DD) : nullptr;
    float sc = s_scale[lr];
    // B loader: two 16B-strided halves -> each 8-lane phase spans 128B (conflict-free)
    int rb = tid >> 4;              // 0..15
    int cb = (tid & 15) * 4;        // 0..60

    for (int k0 = 0; k0 < DD; k0 += 16) {
        float4 av0 = make_float4(0.f, 0.f, 0.f, 0.f);
        float4 av1 = make_float4(0.f, 0.f, 0.f, 0.f);
        if (Arow) {
            av0 = *(const float4*)(Arow + k0 + lc);
            av1 = *(const float4*)(Arow + k0 + lc + 4);
            av0.x *= sc; av0.y *= sc; av0.z *= sc; av0.w *= sc;
            av1.x *= sc; av1.y *= sc; av1.z *= sc; av1.w *= sc;
        }
        As[lc + 0][lr] = av0.x; As[lc + 1][lr] = av0.y;
        As[lc + 2][lr] = av0.z; As[lc + 3][lr] = av0.w;
        As[lc + 4][lr] = av1.x; As[lc + 5][lr] = av1.y;
        As[lc + 6][lr] = av1.z; As[lc + 7][lr] = av1.w;
        *(float4*)&Bs[rb][cb]      = *(const float4*)(W + (size_t)(k0 + rb) * DD + cb);
        *(float4*)&Bs[rb][64 + cb] = *(const float4*)(W + (size_t)(k0 + rb) * DD + 64 + cb);
        __syncthreads();
#pragma unroll
        for (int kk = 0; kk < 16; kk++) {
            float4 a0 = *(float4*)&As[kk][ty * 4];
            float4 a1 = *(float4*)&As[kk][64 + ty * 4];
            float4 b0 = *(float4*)&Bs[kk][tx * 4];
            float4 b1 = *(float4*)&Bs[kk][64 + tx * 4];
            float a[8] = {a0.x, a0.y, a0.z, a0.w, a1.x, a1.y, a1.z, a1.w};
            float b[8] = {b0.x, b0.y, b0.z, b0.w, b1.x, b1.y, b1.z, b1.w};
#pragma unroll
            for (int i = 0; i < 8; i++)
#pragma unroll
                for (int j = 0; j < 8; j++)
                    acc[i][j] = fmaf(a[i], b[j], acc[i][j]);
        }
        __syncthreads();
    }

    const float* bias = ga.bias[z] + (size_t)t * DD + blockIdx.y * 128;
    float4 bv0 = *(const float4*)(bias + tx * 4);
    float4 bv1 = *(const float4*)(bias + 64 + tx * 4);
    float* out = ga.out[z];
#pragma unroll
    for (int i = 0; i < 8; i++) {
        int rloc = (i < 4) ? (ty * 4 + i) : (64 + ty * 4 + i - 4);
        int nd = s_nodes[rloc];
        if (nd < 0) continue;
        float* o = out + (size_t)nd * DD + blockIdx.y * 128;
        float4 v0, v1;
        v0.x = acc[i][0] + bv0.x; v0.y = acc[i][1] + bv0.y;
        v0.z = acc[i][2] + bv0.z; v0.w = acc[i][3] + bv0.w;
        v1.x = acc[i][4] + bv1.x; v1.y = acc[i][5] + bv1.y;
        v1.z = acc[i][6] + bv1.z; v1.w = acc[i][7] + bv1.w;
        *(float4*)(o + tx * 4)      = v0;
        *(float4*)(o + 64 + tx * 4) = v1;
    }
}

// ---------------- relation transforms as batched GEMM per (phase, r, h):
// dst[r, node, h*64+e] = sum_d src[node, h*64+d] * W[r,h,d,e]
// BM=128, BN=64, K=64 (BK=16), 256 threads, 8x4 micro-tile. B tile fully resident in smem.
__global__ __launch_bounds__(256) void rel_transform(const float* __restrict__ Watt,
                                                     const float* __restrict__ Wmsg,
                                                     int n) {
    __shared__ float As[16][132];
    __shared__ float Bs[64][64];

    int tid = threadIdx.x;
    int z = blockIdx.z;              // 0..47
    int phase = z / 24;              // 0: k/att, 1: v/msg
    int r = (z % 24) >> 2;
    int h = z & 3;

    const float* src = phase ? g_v : g_k;
    const float* Wp  = (phase ? Wmsg : Watt) + ((size_t)r * HH + h) * DKK * DKK;
    float* dst       = phase ? g_vrel : g_krel;

    int row0 = blockIdx.x * 128;
    int tx = tid & 15, ty = tid >> 4;

    float acc[8][4];
#pragma unroll
    for (int i = 0; i < 8; i++)
#pragma unroll
        for (int j = 0; j < 4; j++) acc[i][j] = 0.f;

    int lr = tid & 127;
    int lc = (tid >> 7) * 8;
    int node_l = row0 + lr;
    const float* Arow = (node_l < n) ? (src + (size_t)node_l * DD + h * DKK) : nullptr;

    for (int k0 = 0; k0 < DKK; k0 += 16) {
        if (k0 == 0) {
            // load full 64x64 B tile once (contiguous, conflict-free)
            for (int i = tid; i < DKK * DKK / 4; i += 256)
                *(float4*)&Bs[0][i * 4] = *(const float4*)(Wp + i * 4);
        }
        float4 av0 = make_float4(0.f, 0.f, 0.f, 0.f);
        float4 av1 = make_float4(0.f, 0.f, 0.f, 0.f);
        if (Arow) {
            av0 = *(const float4*)(Arow + k0 + lc);
            av1 = *(const float4*)(Arow + k0 + lc + 4);
        }
        As[lc + 0][lr] = av0.x; As[lc + 1][lr] = av0.y;
        As[lc + 2][lr] = av0.z; As[lc + 3][lr] = av0.w;
        As[lc + 4][lr] = av1.x; As[lc + 5][lr] = av1.y;
        As[lc + 6][lr] = av1.z; As[lc + 7][lr] = av1.w;
        __syncthreads();
#pragma unroll
        for (int kk = 0; kk < 16; kk++) {
            float4 a0 = *(float4*)&As[kk][ty * 4];
            float4 a1 = *(float4*)&As[kk][64 + ty * 4];
            float4 b  = *(float4*)&Bs[k0 + kk][tx * 4];
            float a[8] = {a0.x, a0.y, a0.z, a0.w, a1.x, a1.y, a1.z, a1.w};
#pragma unroll
            for (int i = 0; i < 8; i++) {
                acc[i][0] = fmaf(a[i], b.x, acc[i][0]);
                acc[i][1] = fmaf(a[i], b.y, acc[i][1]);
                acc[i][2] = fmaf(a[i], b.z, acc[i][2]);
                acc[i][3] = fmaf(a[i], b.w, acc[i][3]);
            }
        }
        __syncthreads();
    }

#pragma unroll
    for (int i = 0; i < 8; i++) {
        int rloc = (i < 4) ? (ty * 4 + i) : (64 + ty * 4 + i - 4);
        int node = row0 + rloc;
        if (node < n) {
            float4 v = make_float4(acc[i][0], acc[i][1], acc[i][2], acc[i][3]);
            *(float4*)(dst + ((size_t)r * n + node) * DD + h * DKK + tx * 4) = v;
        }
    }
}

// ---------------- edge pass 1: att -> exp, segment denom (softmax shift-invariant; max skipped)
__global__ void edge_att(const int* __restrict__ esrc, const int* __restrict__ edst,
                         const int* __restrict__ etype, const float* __restrict__ rel_pri,
                         int ne, int n) {
    int e = blockIdx.x * 8 + (threadIdx.x >> 5);
    if (e >= ne) return;
    int L = threadIdx.x & 31;
    int src = esrc[e], dst = edst[e], r = etype[e];

    const float4* qp = (const float4*)(g_q + (size_t)dst * DD) + L * 2;
    const float4* kp = (const float4*)(g_krel + ((size_t)r * n + src) * DD) + L * 2;
    float4 q0 = qp[0], q1 = qp[1];
    float4 k0 = kp[0], k1 = kp[1];
    float s = q0.x * k0.x + q0.y * k0.y + q0.z * k0.z + q0.w * k0.w
            + q1.x * k1.x + q1.y * k1.y + q1.z * k1.z + q1.w * k1.w;
    s += __shfl_xor_sync(0xffffffffu, s, 1);
    s += __shfl_xor_sync(0xffffffffu, s, 2);
    s += __shfl_xor_sync(0xffffffffu, s, 4);
    if ((L & 7) == 0) {
        int h = L >> 3;
        float att = s * rel_pri[r * HH + h] * 0.125f;   // 1/sqrt(64)
        float ex = expf(att);
        g_ex[(size_t)e * HH + h] = ex;
        atomicAdd(&g_denom[((size_t)dst * RR + r) * HH + h], ex);
    }
}

// ---------------- edge pass 2: t[dst] += w * v_rel[r,src]  (vectorized L2 reductions)
__global__ void edge_aggregate(const int* __restrict__ esrc, const int* __restrict__ edst,
                               const int* __restrict__ etype, int ne, int n) {
    int e = blockIdx.x * 8 + (threadIdx.x >> 5);
    if (e >= ne) return;
    int L = threadIdx.x & 31;
    int src = esrc[e], dst = edst[e], r = etype[e];
    int h = L >> 3;
    float w = g_ex[(size_t)e * HH + h] / g_denom[((size_t)dst * RR + r) * HH + h];

    const float4* vp = (const float4*)(g_vrel + ((size_t)r * n + src) * DD) + L * 2;
    float4 v0 = vp[0], v1 = vp[1];
    float* tp = g_t + (size_t)dst * DD + L * 8;
    asm volatile("red.global.add.v4.f32 [%0], {%1,%2,%3,%4};"
                 :: "l"(tp), "f"(v0.x * w), "f"(v0.y * w), "f"(v0.z * w), "f"(v0.w * w)
                 : "memory");
    asm volatile("red.global.add.v4.f32 [%0], {%1,%2,%3,%4};"
                 :: "l"(tp + 4), "f"(v1.x * w), "f"(v1.y * w), "f"(v1.z * w), "f"(v1.w * w)
                 : "memory");
}

// ---------------- per-node: relation count -> 1/nrel, has_msg
__global__ void node_nrel(int n) {
    int i = blockIdx.x * blockDim.x + threadIdx.x;
    if (i >= n) return;
    int c = 0;
#pragma unroll
    for (int r = 0; r < RR; r++)
        c += (g_denom[((size_t)i * RR + r) * HH] > 0.f) ? 1 : 0;
    g_hasmsg[i] = (c > 0) ? 1 : 0;
    g_invnrel[i] = 1.0f / (float)(c > 0 ? c : 1);
}

// ---------------- final: gated residual + layernorm + no-message passthrough (warp per node)
__global__ void finalize(const float* __restrict__ x, const float* __restrict__ skip,
                         const float* __restrict__ ln_g, const float* __restrict__ ln_b,
                         const int* __restrict__ nt, float* __restrict__ out, int n) {
    int node = blockIdx.x * 8 + (threadIdx.x >> 5);
    if (node >= n) return;
    int L = threadIdx.x & 31;
    int t = nt[node];
    float alpha = 1.0f / (1.0f + expf(-skip[t]));
    float beta = 1.0f - alpha;

    const float4* xp = (const float4*)(x + (size_t)node * DD) + L * 2;
    const float4* tp = (const float4*)(g_trans + (size_t)node * DD) + L * 2;
    float4 x0 = xp[0], x1 = xp[1];
    float4 t0 = tp[0], t1 = tp[1];

    float o[8];
    o[0] = t0.x * alpha + x0.x * beta;
    o[1] = t0.y * alpha + x0.y * beta;
    o[2] = t0.z * alpha + x0.z * beta;
    o[3] = t0.w * alpha + x0.w * beta;
    o[4] = t1.x * alpha + x1.x * beta;
    o[5] = t1.y * alpha + x1.y * beta;
    o[6] = t1.z * alpha + x1.z * beta;
    o[7] = t1.w * alpha + x1.w * beta;

    float s = 0.f, s2 = 0.f;
#pragma unroll
    for (int j = 0; j < 8; j++) { s += o[j]; s2 += o[j] * o[j]; }
#pragma unroll
    for (int off = 16; off > 0; off >>= 1) {
        s  += __shfl_xor_sync(0xffffffffu, s, off);
        s2 += __shfl_xor_sync(0xffffffffu, s2, off);
    }
    float mu = s * (1.0f / DD);
    float var = s2 * (1.0f / DD) - mu * mu;
    float rstd = rsqrtf(var + 1e-5f);

    float4 r0, r1;
    if (g_hasmsg[node]) {
        const float4* gp = (const float4*)(ln_g + (size_t)t * DD) + L * 2;
        const float4* bp = (const float4*)(ln_b + (size_t)t * DD) + L * 2;
        float4 g0 = gp[0], g1 = gp[1];
        float4 b0 = bp[0], b1 = bp[1];
        r0.x = (o[0] - mu) * rstd * g0.x + b0.x;
        r0.y = (o[1] - mu) * rstd * g0.y + b0.y;
        r0.z = (o[2] - mu) * rstd * g0.z + b0.z;
        r0.w = (o[3] - mu) * rstd * g0.w + b0.w;
        r1.x = (o[4] - mu) * rstd * g1.x + b1.x;
        r1.y = (o[5] - mu) * rstd * g1.y + b1.y;
        r1.z = (o[6] - mu) * rstd * g1.z + b1.z;
        r1.w = (o[7] - mu) * rstd * g1.w + b1.w;
    } else {
        r0 = x0; r1 = x1;
    }
    float4* op = (float4*)(out + (size_t)node * DD) + L * 2;
    op[0] = r0;
    op[1] = r1;
}

// ---------------- host launcher ----------------
extern "C" void kernel_launch(void* const* d_in, const int* in_sizes, int n_in,
                              void* d_out, int out_size) {
    const float* x       = (const float*)d_in[0];
    const float* Wk      = (const float*)d_in[1];
    const float* bk      = (const float*)d_in[2];
    const float* Wq      = (const float*)d_in[3];
    const float* bq      = (const float*)d_in[4];
    const float* Wv      = (const float*)d_in[5];
    const float* bv      = (const float*)d_in[6];
    const float* Wa      = (const float*)d_in[7];
    const float* ba      = (const float*)d_in[8];
    const float* rel_pri = (const float*)d_in[9];
    const float* rel_att = (const float*)d_in[10];
    const float* rel_msg = (const float*)d_in[11];
    const float* skip    = (const float*)d_in[12];
    const float* ln_g    = (const float*)d_in[13];
    const float* ln_b    = (const float*)d_in[14];
    const int* node_type = (const int*)d_in[15];
    const int* edge_src  = (const int*)d_in[16];
    const int* edge_dst  = (const int*)d_in[17];
    const int* edge_type = (const int*)d_in[18];

    int n  = in_sizes[0] / DD;
    int ne = in_sizes[16];
    if (n > NN || ne > EE) return;  // sized for the benchmark shapes

    void *p_cnt, *p_cursor, *p_perm, *p_denom, *p_t;
    void *p_k, *p_q, *p_v, *p_trans, *p_invnrel;
    cudaGetSymbolAddress(&p_cnt, g_cnt);
    cudaGetSymbolAddress(&p_cursor, g_cursor);
    cudaGetSymbolAddress(&p_perm, g_perm);
    cudaGetSymbolAddress(&p_denom, g_denom);
    cudaGetSymbolAddress(&p_t, g_t);
    cudaGetSymbolAddress(&p_k, g_k);
    cudaGetSymbolAddress(&p_q, g_q);
    cudaGetSymbolAddress(&p_v, g_v);
    cudaGetSymbolAddress(&p_trans, g_trans);
    cudaGetSymbolAddress(&p_invnrel, g_invnrel);

    cudaMemsetAsync(p_cnt, 0, sizeof(int) * TT);
    cudaMemsetAsync(p_cursor, 0, sizeof(int) * TT);
    cudaMemsetAsync(p_perm, 0xFF, sizeof(int) * NPADMAX);
    cudaMemsetAsync(p_denom, 0, sizeof(float) * (size_t)n * RR * HH);
    cudaMemsetAsync(p_t, 0, sizeof(float) * (size_t)n * DD);

    // type bucketing
    count_types<<<(n + 255) / 256, 256>>>(node_type, n);
    make_offsets<<<1, 1>>>();
    scatter_perm<<<(n + 255) / 256, 256>>>(node_type, n);

    // fused KQV typed linears (grid.z = {k,q,v})
    GemmArgs g1;
    g1.A = x; g1.scale = nullptr;
    g1.W[0] = Wk; g1.W[1] = Wq; g1.W[2] = Wv;
    g1.bias[0] = bk; g1.bias[1] = bq; g1.bias[2] = bv;
    g1.out[0] = (float*)p_k; g1.out[1] = (float*)p_q; g1.out[2] = (float*)p_v;
    dim3 grid1((n + 127) / 128 + TT, DD / 128, 3);
    typed_gemm<<<grid1, 256>>>(g1);

    // relation transforms: batched GEMM over (phase, r, h)
    dim3 gridR((n + 127) / 128, 1, 2 * RR * HH);
    rel_transform<<<gridR, 256>>>(rel_att, rel_msg, n);

    // edge passes
    edge_att<<<(ne + 7) / 8, 256>>>(edge_src, edge_dst, edge_type, rel_pri, ne, n);
    edge_aggregate<<<(ne + 7) / 8, 256>>>(edge_src, edge_dst, edge_type, ne, n);
    node_nrel<<<(n + 255) / 256, 256>>>(n);

    // output typed linear (with 1/nrel row scaling)
    GemmArgs g2;
    g2.A = (const float*)p_t; g2.scale = (const float*)p_invnrel;
    g2.W[0] = Wa; g2.W[1] = Wa; g2.W[2] = Wa;
    g2.bias[0] = ba; g2.bias[1] = ba; g2.bias[2] = ba;
    g2.out[0] = (float*)p_trans; g2.out[1] = (float*)p_trans; g2.out[2] = (float*)p_trans;
    dim3 grid2((n + 127) / 128 + TT, DD / 128, 1);
    typed_gemm<<<grid2, 256>>>(g2);

    // gated residual + LN + passthrough
    finalize<<<(n + 7) / 8, 256>>>(x, skip, ln_g, ln_b, node_type, (float*)d_out, n);
}

// round 5
// speedup vs baseline: 1.4147x; 1.0611x over previous
#include <cuda_runtime.h>
#include <math.h>
#include <stdint.h>

#define TT 3
#define RR 6
#define HH 4
#define DKK 64
#define DD 256
#define NN 50000
#define EE 400000
#define NPADMAX (NN + TT * 128)

// ---------------- scratch (device globals: sanctioned, no runtime alloc) ----------------
__device__ float g_k[(size_t)NN * DD];
__device__ float g_q[(size_t)NN * DD];
__device__ float g_v[(size_t)NN * DD];
__device__ float g_t[(size_t)NN * DD];
__device__ float g_trans[(size_t)NN * DD];
__device__ float g_krel[(size_t)RR * NN * DD];
__device__ float g_vrel[(size_t)RR * NN * DD];
__device__ float g_ex[(size_t)EE * HH];
__device__ float g_denom[(size_t)NN * RR * HH];
__device__ float g_invnrel[NN];
__device__ int   g_hasmsg[NN];
__device__ int   g_perm[NPADMAX];
__device__ int   g_cnt[TT];
__device__ int   g_cursor[TT];
__device__ int   g_padoff[TT + 1];

// ---------------- type bucketing (counting sort by node type, 128-padded segments) --------
__global__ void count_types(const int* __restrict__ nt, int n) {
    int i = blockIdx.x * blockDim.x + threadIdx.x;
    if (i < n) atomicAdd(&g_cnt[nt[i]], 1);
}

__global__ void make_offsets() {
    if (threadIdx.x == 0 && blockIdx.x == 0) {
        int off = 0;
        for (int t = 0; t < TT; t++) {
            g_padoff[t] = off;
            off += ((g_cnt[t] + 127) >> 7) << 7;
        }
        g_padoff[TT] = off;
    }
}

__global__ void scatter_perm(const int* __restrict__ nt, int n) {
    int i = blockIdx.x * blockDim.x + threadIdx.x;
    if (i < n) {
        int t = nt[i];
        int pos = g_padoff[t] + atomicAdd(&g_cursor[t], 1);
        g_perm[pos] = i;
    }
}

// ---------------- typed linear GEMM: out[n] = (A[n]*scale[n]) @ W[type(n)] + bias[type(n)]
// BM=128, BN=128, BK=16, 256 threads, 8x8 micro-tile, DOUBLE-BUFFERED smem (1 sync/iter).
struct GemmArgs {
    const float* A;
    const float* scale;     // nullptr -> no scaling
    const float* W[3];
    const float* bias[3];
    float*       out[3];
};

__global__ __launch_bounds__(256, 2) void typed_gemm(GemmArgs ga) {
    __shared__ float As[2][16][132];
    __shared__ float Bs[2][16][128];
    __shared__ int   s_nodes[128];
    __shared__ float s_scale[128];

    int row0 = blockIdx.x * 128;
    if (row0 >= g_padoff[TT]) return;
    int t = 0;
#pragma unroll
    for (int tt = 0; tt < TT - 1; tt++)
        if (row0 >= g_padoff[tt + 1]) t = tt + 1;

    int tid = threadIdx.x;
    if (tid < 128) {
        int nd = g_perm[row0 + tid];
        s_nodes[tid] = nd;
        s_scale[tid] = (ga.scale != nullptr && nd >= 0) ? ga.scale[nd] : 1.0f;
    }
    __syncthreads();

    int z = blockIdx.z;
    const float* W = ga.W[z] + (size_t)t * DD * DD + blockIdx.y * 128;

    int tx = tid & 15, ty = tid >> 4;
    float acc[8][8];
#pragma unroll
    for (int i = 0; i < 8; i++)
#pragma unroll
        for (int j = 0; j < 8; j++) acc[i][j] = 0.f;

    // A loader: lr = tid&127 (32 distinct rows per warp -> conflict-free transpose STS)
    int lr = tid & 127;
    int lc = (tid >> 7) * 8;        // 0 or 8
    int nd_l = s_nodes[lr];
    const float* Arow = (nd_l >= 0) ? (ga.A + (size_t)nd_l * DD) : nullptr;
    float sc = s_scale[lr];
    // B loader
    int rb = tid >> 4;              // 0..15
    int cb = (tid & 15) * 4;        // 0..60

    // prologue: tile k0=0 -> buf 0
    {
        float4 av0 = make_float4(0.f,0.f,0.f,0.f), av1 = av0;
        if (Arow) {
            av0 = *(const float4*)(Arow + lc);
            av1 = *(const float4*)(Arow + lc + 4);
            av0.x *= sc; av0.y *= sc; av0.z *= sc; av0.w *= sc;
            av1.x *= sc; av1.y *= sc; av1.z *= sc; av1.w *= sc;
        }
        As[0][lc + 0][lr] = av0.x; As[0][lc + 1][lr] = av0.y;
        As[0][lc + 2][lr] = av0.z; As[0][lc + 3][lr] = av0.w;
        As[0][lc + 4][lr] = av1.x; As[0][lc + 5][lr] = av1.y;
        As[0][lc + 6][lr] = av1.z; As[0][lc + 7][lr] = av1.w;
        *(float4*)&Bs[0][rb][cb]      = *(const float4*)(W + (size_t)rb * DD + cb);
        *(float4*)&Bs[0][rb][64 + cb] = *(const float4*)(W + (size_t)rb * DD + 64 + cb);
    }
    __syncthreads();

    int buf = 0;
    for (int k0 = 0; k0 < DD; k0 += 16) {
        bool more = (k0 + 16) < DD;
        float4 pa0 = make_float4(0.f,0.f,0.f,0.f), pa1 = pa0, pb0, pb1;
        if (more) {
            if (Arow) {
                pa0 = *(const float4*)(Arow + k0 + 16 + lc);
                pa1 = *(const float4*)(Arow + k0 + 16 + lc + 4);
                pa0.x *= sc; pa0.y *= sc; pa0.z *= sc; pa0.w *= sc;
                pa1.x *= sc; pa1.y *= sc; pa1.z *= sc; pa1.w *= sc;
            }
            pb0 = *(const float4*)(W + (size_t)(k0 + 16 + rb) * DD + cb);
            pb1 = *(const float4*)(W + (size_t)(k0 + 16 + rb) * DD + 64 + cb);
        }
#pragma unroll
        for (int kk = 0; kk < 16; kk++) {
            float4 a0 = *(float4*)&As[buf][kk][ty * 4];
            float4 a1 = *(float4*)&As[buf][kk][64 + ty * 4];
            float4 b0 = *(float4*)&Bs[buf][kk][tx * 4];
            float4 b1 = *(float4*)&Bs[buf][kk][64 + tx * 4];
            float a[8] = {a0.x, a0.y, a0.z, a0.w, a1.x, a1.y, a1.z, a1.w};
            float b[8] = {b0.x, b0.y, b0.z, b0.w, b1.x, b1.y, b1.z, b1.w};
#pragma unroll
            for (int i = 0; i < 8; i++)
#pragma unroll
                for (int j = 0; j < 8; j++)
                    acc[i][j] = fmaf(a[i], b[j], acc[i][j]);
        }
        if (more) {
            int nb = buf ^ 1;
            As[nb][lc + 0][lr] = pa0.x; As[nb][lc + 1][lr] = pa0.y;
            As[nb][lc + 2][lr] = pa0.z; As[nb][lc + 3][lr] = pa0.w;
            As[nb][lc + 4][lr] = pa1.x; As[nb][lc + 5][lr] = pa1.y;
            As[nb][lc + 6][lr] = pa1.z; As[nb][lc + 7][lr] = pa1.w;
            *(float4*)&Bs[nb][rb][cb]      = pb0;
            *(float4*)&Bs[nb][rb][64 + cb] = pb1;
        }
        __syncthreads();
        buf ^= 1;
    }

    const float* bias = ga.bias[z] + (size_t)t * DD + blockIdx.y * 128;
    float4 bv0 = *(const float4*)(bias + tx * 4);
    float4 bv1 = *(const float4*)(bias + 64 + tx * 4);
    float* out = ga.out[z];
#pragma unroll
    for (int i = 0; i < 8; i++) {
        int rloc = (i < 4) ? (ty * 4 + i) : (64 + ty * 4 + i - 4);
        int nd = s_nodes[rloc];
        if (nd < 0) continue;
        float* o = out + (size_t)nd * DD + blockIdx.y * 128;
        float4 v0, v1;
        v0.x = acc[i][0] + bv0.x; v0.y = acc[i][1] + bv0.y;
        v0.z = acc[i][2] + bv0.z; v0.w = acc[i][3] + bv0.w;
        v1.x = acc[i][4] + bv1.x; v1.y = acc[i][5] + bv1.y;
        v1.z = acc[i][6] + bv1.z; v1.w = acc[i][7] + bv1.w;
        *(float4*)(o + tx * 4)      = v0;
        *(float4*)(o + 64 + tx * 4) = v1;
    }
}

// ---------------- relation transforms: dst[r,node,h*64+e] = sum_d src[node,h*64+d] * W[r,h,d,e]
// Block = 256 nodes x one (phase,h). A tile (256x64) staged TRANSPOSED in smem ONCE,
// then reused across all 6 relations. 8x8 micro-tile (1 B smem / FMA). Dynamic smem 84KB.
__global__ __launch_bounds__(256) void rel_transform(const float* __restrict__ Watt,
                                                     const float* __restrict__ Wmsg,
                                                     int n) {
    extern __shared__ float sm[];
    float (*As)[264] = (float (*)[264])sm;            // [64][264] : [k][node]
    float (*Bs)[64]  = (float (*)[64])(sm + 64 * 264); // [64][64]  : [k][e]

    int tid = threadIdx.x;
    int z = blockIdx.z;              // 0..7
    int phase = z >> 2;
    int h = z & 3;

    const float* src   = phase ? g_v : g_k;
    const float* Wbase = phase ? Wmsg : Watt;
    float* dst         = phase ? g_vrel : g_krel;

    int row0 = blockIdx.x * 256;
    int tx = tid & 7, ty = tid >> 3;   // 8 cols x 32 row-groups

    // stage A transposed: thread tid owns node row0+tid (64 contiguous floats)
    {
        int node = row0 + tid;
        if (node < n) {
            const float* Arow = src + (size_t)node * DD + h * DKK;
#pragma unroll
            for (int i = 0; i < 16; i++) {
                float4 v = *(const float4*)(Arow + i * 4);
                As[i * 4 + 0][tid] = v.x;
                As[i * 4 + 1][tid] = v.y;
                As[i * 4 + 2][tid] = v.z;
                As[i * 4 + 3][tid] = v.w;
            }
        } else {
#pragma unroll
            for (int i = 0; i < 64; i++) As[i][tid] = 0.f;
        }
    }

    for (int r = 0; r < RR; r++) {
        __syncthreads();   // protect Bs overwrite (and A visibility on first iter)
        const float* Wp = Wbase + ((size_t)r * HH + h) * DKK * DKK;
        for (int i = tid; i < DKK * DKK / 4; i += 256)
            ((float4*)Bs)[i] = ((const float4*)Wp)[i];
        __syncthreads();

        float acc[8][8];
#pragma unroll
        for (int i = 0; i < 8; i++)
#pragma unroll
            for (int j = 0; j < 8; j++) acc[i][j] = 0.f;

#pragma unroll 16
        for (int kk = 0; kk < DKK; kk++) {
            float4 a0 = *(float4*)&As[kk][ty * 8];
            float4 a1 = *(float4*)&As[kk][ty * 8 + 4];
            float4 b0 = *(float4*)&Bs[kk][tx * 8];
            float4 b1 = *(float4*)&Bs[kk][tx * 8 + 4];
            float a[8] = {a0.x, a0.y, a0.z, a0.w, a1.x, a1.y, a1.z, a1.w};
            float b[8] = {b0.x, b0.y, b0.z, b0.w, b1.x, b1.y, b1.z, b1.w};
#pragma unroll
            for (int i = 0; i < 8; i++)
#pragma unroll
                for (int j = 0; j < 8; j++)
                    acc[i][j] = fmaf(a[i], b[j], acc[i][j]);
        }

#pragma unroll
        for (int i = 0; i < 8; i++) {
            int node = row0 + ty * 8 + i;
            if (node < n) {
                float* o = dst + ((size_t)r * n + node) * DD + h * DKK + tx * 8;
                *(float4*)o       = make_float4(acc[i][0], acc[i][1], acc[i][2], acc[i][3]);
                *(float4*)(o + 4) = make_float4(acc[i][4], acc[i][5], acc[i][6], acc[i][7]);
            }
        }
    }
}

// ---------------- edge pass 1: att -> exp, segment denom (softmax shift-invariant; max skipped)
__global__ void edge_att(const int* __restrict__ esrc, const int* __restrict__ edst,
                         const int* __restrict__ etype, const float* __restrict__ rel_pri,
                         int ne, int n) {
    int e = blockIdx.x * 8 + (threadIdx.x >> 5);
    if (e >= ne) return;
    int L = threadIdx.x & 31;
    int src = esrc[e], dst = edst[e], r = etype[e];

    const float4* qp = (const float4*)(g_q + (size_t)dst * DD) + L * 2;
    const float4* kp = (const float4*)(g_krel + ((size_t)r * n + src) * DD) + L * 2;
    float4 q0 = qp[0], q1 = qp[1];
    float4 k0 = kp[0], k1 = kp[1];
    float s = q0.x * k0.x + q0.y * k0.y + q0.z * k0.z + q0.w * k0.w
            + q1.x * k1.x + q1.y * k1.y + q1.z * k1.z + q1.w * k1.w;
    s += __shfl_xor_sync(0xffffffffu, s, 1);
    s += __shfl_xor_sync(0xffffffffu, s, 2);
    s += __shfl_xor_sync(0xffffffffu, s, 4);
    if ((L & 7) == 0) {
        int h = L >> 3;
        float att = s * rel_pri[r * HH + h] * 0.125f;   // 1/sqrt(64)
        float ex = expf(att);
        g_ex[(size_t)e * HH + h] = ex;
        atomicAdd(&g_denom[((size_t)dst * RR + r) * HH + h], ex);
    }
}

// ---------------- edge pass 2: t[dst] += w * v_rel[r,src]  (vectorized L2 reductions)
__global__ void edge_aggregate(const int* __restrict__ esrc, const int* __restrict__ edst,
                               const int* __restrict__ etype, int ne, int n) {
    int e = blockIdx.x * 8 + (threadIdx.x >> 5);
    if (e >= ne) return;
    int L = threadIdx.x & 31;
    int src = esrc[e], dst = edst[e], r = etype[e];
    int h = L >> 3;
    float w = g_ex[(size_t)e * HH + h] / g_denom[((size_t)dst * RR + r) * HH + h];

    const float4* vp = (const float4*)(g_vrel + ((size_t)r * n + src) * DD) + L * 2;
    float4 v0 = vp[0], v1 = vp[1];
    float* tp = g_t + (size_t)dst * DD + L * 8;
    asm volatile("red.global.add.v4.f32 [%0], {%1,%2,%3,%4};"
                 :: "l"(tp), "f"(v0.x * w), "f"(v0.y * w), "f"(v0.z * w), "f"(v0.w * w)
                 : "memory");
    asm volatile("red.global.add.v4.f32 [%0], {%1,%2,%3,%4};"
                 :: "l"(tp + 4), "f"(v1.x * w), "f"(v1.y * w), "f"(v1.z * w), "f"(v1.w * w)
                 : "memory");
}

// ---------------- per-node: relation count -> 1/nrel, has_msg
__global__ void node_nrel(int n) {
    int i = blockIdx.x * blockDim.x + threadIdx.x;
    if (i >= n) return;
    int c = 0;
#pragma unroll
    for (int r = 0; r < RR; r++)
        c += (g_denom[((size_t)i * RR + r) * HH] > 0.f) ? 1 : 0;
    g_hasmsg[i] = (c > 0) ? 1 : 0;
    g_invnrel[i] = 1.0f / (float)(c > 0 ? c : 1);
}

// ---------------- final: gated residual + layernorm + no-message passthrough (warp per node)
__global__ void finalize(const float* __restrict__ x, const float* __restrict__ skip,
                         const float* __restrict__ ln_g, const float* __restrict__ ln_b,
                         const int* __restrict__ nt, float* __restrict__ out, int n) {
    int node = blockIdx.x * 8 + (threadIdx.x >> 5);
    if (node >= n) return;
    int L = threadIdx.x & 31;
    int t = nt[node];
    float alpha = 1.0f / (1.0f + expf(-skip[t]));
    float beta = 1.0f - alpha;

    const float4* xp = (const float4*)(x + (size_t)node * DD) + L * 2;
    const float4* tp = (const float4*)(g_trans + (size_t)node * DD) + L * 2;
    float4 x0 = xp[0], x1 = xp[1];
    float4 t0 = tp[0], t1 = tp[1];

    float o[8];
    o[0] = t0.x * alpha + x0.x * beta;
    o[1] = t0.y * alpha + x0.y * beta;
    o[2] = t0.z * alpha + x0.z * beta;
    o[3] = t0.w * alpha + x0.w * beta;
    o[4] = t1.x * alpha + x1.x * beta;
    o[5] = t1.y * alpha + x1.y * beta;
    o[6] = t1.z * alpha + x1.z * beta;
    o[7] = t1.w * alpha + x1.w * beta;

    float s = 0.f, s2 = 0.f;
#pragma unroll
    for (int j = 0; j < 8; j++) { s += o[j]; s2 += o[j] * o[j]; }
#pragma unroll
    for (int off = 16; off > 0; off >>= 1) {
        s  += __shfl_xor_sync(0xffffffffu, s, off);
        s2 += __shfl_xor_sync(0xffffffffu, s2, off);
    }
    float mu = s * (1.0f / DD);
    float var = s2 * (1.0f / DD) - mu * mu;
    float rstd = rsqrtf(var + 1e-5f);

    float4 r0, r1;
    if (g_hasmsg[node]) {
        const float4* gp = (const float4*)(ln_g + (size_t)t * DD) + L * 2;
        const float4* bp = (const float4*)(ln_b + (size_t)t * DD) + L * 2;
        float4 g0 = gp[0], g1 = gp[1];
        float4 b0 = bp[0], b1 = bp[1];
        r0.x = (o[0] - mu) * rstd * g0.x + b0.x;
        r0.y = (o[1] - mu) * rstd * g0.y + b0.y;
        r0.z = (o[2] - mu) * rstd * g0.z + b0.z;
        r0.w = (o[3] - mu) * rstd * g0.w + b0.w;
        r1.x = (o[4] - mu) * rstd * g1.x + b1.x;
        r1.y = (o[5] - mu) * rstd * g1.y + b1.y;
        r1.z = (o[6] - mu) * rstd * g1.z + b1.z;
        r1.w = (o[7] - mu) * rstd * g1.w + b1.w;
    } else {
        r0 = x0; r1 = x1;
    }
    float4* op = (float4*)(out + (size_t)node * DD) + L * 2;
    op[0] = r0;
    op[1] = r1;
}

// ---------------- host launcher ----------------
extern "C" void kernel_launch(void* const* d_in, const int* in_sizes, int n_in,
                              void* d_out, int out_size) {
    const float* x       = (const float*)d_in[0];
    const float* Wk      = (const float*)d_in[1];
    const float* bk      = (const float*)d_in[2];
    const float* Wq      = (const float*)d_in[3];
    const float* bq      = (const float*)d_in[4];
    const float* Wv      = (const float*)d_in[5];
    const float* bv      = (const float*)d_in[6];
    const float* Wa      = (const float*)d_in[7];
    const float* ba      = (const float*)d_in[8];
    const float* rel_pri = (const float*)d_in[9];
    const float* rel_att = (const float*)d_in[10];
    const float* rel_msg = (const float*)d_in[11];
    const float* skip    = (const float*)d_in[12];
    const float* ln_g    = (const float*)d_in[13];
    const float* ln_b    = (const float*)d_in[14];
    const int* node_type = (const int*)d_in[15];
    const int* edge_src  = (const int*)d_in[16];
    const int* edge_dst  = (const int*)d_in[17];
    const int* edge_type = (const int*)d_in[18];

    int n  = in_sizes[0] / DD;
    int ne = in_sizes[16];
    if (n > NN || ne > EE) return;  // sized for the benchmark shapes

    void *p_cnt, *p_cursor, *p_perm, *p_denom, *p_t;
    void *p_k, *p_q, *p_v, *p_trans, *p_invnrel;
    cudaGetSymbolAddress(&p_cnt, g_cnt);
    cudaGetSymbolAddress(&p_cursor, g_cursor);
    cudaGetSymbolAddress(&p_perm, g_perm);
    cudaGetSymbolAddress(&p_denom, g_denom);
    cudaGetSymbolAddress(&p_t, g_t);
    cudaGetSymbolAddress(&p_k, g_k);
    cudaGetSymbolAddress(&p_q, g_q);
    cudaGetSymbolAddress(&p_v, g_v);
    cudaGetSymbolAddress(&p_trans, g_trans);
    cudaGetSymbolAddress(&p_invnrel, g_invnrel);

    cudaMemsetAsync(p_cnt, 0, sizeof(int) * TT);
    cudaMemsetAsync(p_cursor, 0, sizeof(int) * TT);
    cudaMemsetAsync(p_perm, 0xFF, sizeof(int) * NPADMAX);
    cudaMemsetAsync(p_denom, 0, sizeof(float) * (size_t)n * RR * HH);
    cudaMemsetAsync(p_t, 0, sizeof(float) * (size_t)n * DD);

    // type bucketing
    count_types<<<(n + 255) / 256, 256>>>(node_type, n);
    make_offsets<<<1, 1>>>();
    scatter_perm<<<(n + 255) / 256, 256>>>(node_type, n);

    // fused KQV typed linears (grid.z = {k,q,v})
    GemmArgs g1;
    g1.A = x; g1.scale = nullptr;
    g1.W[0] = Wk; g1.W[1] = Wq; g1.W[2] = Wv;
    g1.bias[0] = bk; g1.bias[1] = bq; g1.bias[2] = bv;
    g1.out[0] = (float*)p_k; g1.out[1] = (float*)p_q; g1.out[2] = (float*)p_v;
    dim3 grid1((n + 127) / 128 + TT, DD / 128, 3);
    typed_gemm<<<grid1, 256>>>(g1);

    // relation transforms: batched GEMM, A-tile reused across all 6 relations
    int relSmem = (64 * 264 + 64 * 64) * sizeof(float);   // ~84KB
    cudaFuncSetAttribute(rel_transform, cudaFuncAttributeMaxDynamicSharedMemorySize, relSmem);
    dim3 gridR((n + 255) / 256, 1, 2 * HH);
    rel_transform<<<gridR, 256, relSmem>>>(rel_att, rel_msg, n);

    // edge passes
    edge_att<<<(ne + 7) / 8, 256>>>(edge_src, edge_dst, edge_type, rel_pri, ne, n);
    edge_aggregate<<<(ne + 7) / 8, 256>>>(edge_src, edge_dst, edge_type, ne, n);
    node_nrel<<<(n + 255) / 256, 256>>>(n);

    // output typed linear (with 1/nrel row scaling)
    GemmArgs g2;
    g2.A = (const float*)p_t; g2.scale = (const float*)p_invnrel;
    g2.W[0] = Wa; g2.W[1] = Wa; g2.W[2] = Wa;
    g2.bias[0] = ba; g2.bias[1] = ba; g2.bias[2] = ba;
    g2.out[0] = (float*)p_trans; g2.out[1] = (float*)p_trans; g2.out[2] = (float*)p_trans;
    dim3 grid2((n + 127) / 128 + TT, DD / 128, 1);
    typed_gemm<<<grid2, 256>>>(g2);

    // gated residual + LN + passthrough
    finalize<<<(n + 7) / 8, 256>>>(x, skip, ln_g, ln_b, node_type, (float*)d_out, n);
}

// round 6
// speedup vs baseline: 1.5044x; 1.0634x over previous
#include <cuda_runtime.h>
#include <math.h>
#include <stdint.h>

#define TT 3
#define RR 6
#define HH 4
#define DKK 64
#define DD 256
#define NN 50000
#define EE 400000
#define NPADMAX (NN + TT * 128)

typedef unsigned long long u64;

// ---- packed f32x2 helpers (FFMA2: 2 FMAs per instruction, fma-pipe double rate) ----
__device__ __forceinline__ u64 splat2(float x) {
    u64 r;
    asm("mov.b64 %0, {%1, %1};" : "=l"(r) : "r"(__float_as_uint(x)));
    return r;
}
__device__ __forceinline__ void ffma2(u64& d, u64 a, u64 b) {
    asm("fma.rn.f32x2 %0, %1, %2, %3;" : "=l"(d) : "l"(a), "l"(b), "l"(d));
}
__device__ __forceinline__ float2 unpack2(u64 v) {
    unsigned int lo, hi;
    asm("mov.b64 {%0, %1}, %2;" : "=r"(lo), "=r"(hi) : "l"(v));
    return make_float2(__uint_as_float(lo), __uint_as_float(hi));
}

// ---------------- scratch (device globals: sanctioned, no runtime alloc) ----------------
__device__ float g_k[(size_t)NN * DD];
__device__ float g_q[(size_t)NN * DD];
__device__ float g_v[(size_t)NN * DD];
__device__ float g_t[(size_t)NN * DD];
__device__ float g_trans[(size_t)NN * DD];
__device__ float g_krel[(size_t)RR * NN * DD];
__device__ float g_vrel[(size_t)RR * NN * DD];
__device__ float g_ex[(size_t)EE * HH];
__device__ float g_denom[(size_t)NN * RR * HH];
__device__ float g_invnrel[NN];
__device__ int   g_hasmsg[NN];
__device__ int   g_perm[NPADMAX];
__device__ int   g_cnt[TT];
__device__ int   g_cursor[TT];
__device__ int   g_padoff[TT + 1];

// ---------------- type bucketing (counting sort by node type, 128-padded segments) --------
__global__ void count_types(const int* __restrict__ nt, int n) {
    int i = blockIdx.x * blockDim.x + threadIdx.x;
    if (i < n) atomicAdd(&g_cnt[nt[i]], 1);
}

__global__ void make_offsets() {
    if (threadIdx.x == 0 && blockIdx.x == 0) {
        int off = 0;
        for (int t = 0; t < TT; t++) {
            g_padoff[t] = off;
            off += ((g_cnt[t] + 127) >> 7) << 7;
        }
        g_padoff[TT] = off;
    }
}

__global__ void scatter_perm(const int* __restrict__ nt, int n) {
    int i = blockIdx.x * blockDim.x + threadIdx.x;
    if (i < n) {
        int t = nt[i];
        int pos = g_padoff[t] + atomicAdd(&g_cursor[t], 1);
        g_perm[pos] = i;
    }
}

// ---------------- typed linear GEMM: out[n] = (A[n]*scale[n]) @ W[type(n)] + bias[type(n)]
// BM=128, BN=128, BK=16, 256 threads, 8x8 micro-tile via packed f32x2 FMA, double-buffered.
struct GemmArgs {
    const float* A;
    const float* scale;     // nullptr -> no scaling
    const float* W[3];
    const float* bias[3];
    float*       out[3];
};

__global__ __launch_bounds__(256, 2) void typed_gemm(GemmArgs ga) {
    __shared__ float As[2][16][132];
    __shared__ float Bs[2][16][128];
    __shared__ int   s_nodes[128];
    __shared__ float s_scale[128];

    int row0 = blockIdx.x * 128;
    if (row0 >= g_padoff[TT]) return;
    int t = 0;
#pragma unroll
    for (int tt = 0; tt < TT - 1; tt++)
        if (row0 >= g_padoff[tt + 1]) t = tt + 1;

    int tid = threadIdx.x;
    if (tid < 128) {
        int nd = g_perm[row0 + tid];
        s_nodes[tid] = nd;
        s_scale[tid] = (ga.scale != nullptr && nd >= 0) ? ga.scale[nd] : 1.0f;
    }
    __syncthreads();

    int z = blockIdx.z;
    const float* W = ga.W[z] + (size_t)t * DD * DD + blockIdx.y * 128;

    int tx = tid & 15, ty = tid >> 4;
    u64 acc[8][4];   // 8 rows x 4 packed column-pairs
#pragma unroll
    for (int i = 0; i < 8; i++)
#pragma unroll
        for (int j = 0; j < 4; j++) acc[i][j] = 0ull;

    int lr = tid & 127;
    int lc = (tid >> 7) * 8;        // 0 or 8
    int nd_l = s_nodes[lr];
    const float* Arow = (nd_l >= 0) ? (ga.A + (size_t)nd_l * DD) : nullptr;
    float sc = s_scale[lr];
    int rb = tid >> 4;              // 0..15
    int cb = (tid & 15) * 4;        // 0..60

    // prologue: tile k0=0 -> buf 0
    {
        float4 av0 = make_float4(0.f,0.f,0.f,0.f), av1 = av0;
        if (Arow) {
            av0 = *(const float4*)(Arow + lc);
            av1 = *(const float4*)(Arow + lc + 4);
            av0.x *= sc; av0.y *= sc; av0.z *= sc; av0.w *= sc;
            av1.x *= sc; av1.y *= sc; av1.z *= sc; av1.w *= sc;
        }
        As[0][lc + 0][lr] = av0.x; As[0][lc + 1][lr] = av0.y;
        As[0][lc + 2][lr] = av0.z; As[0][lc + 3][lr] = av0.w;
        As[0][lc + 4][lr] = av1.x; As[0][lc + 5][lr] = av1.y;
        As[0][lc + 6][lr] = av1.z; As[0][lc + 7][lr] = av1.w;
        *(float4*)&Bs[0][rb][cb]      = *(const float4*)(W + (size_t)rb * DD + cb);
        *(float4*)&Bs[0][rb][64 + cb] = *(const float4*)(W + (size_t)rb * DD + 64 + cb);
    }
    __syncthreads();

    int buf = 0;
    for (int k0 = 0; k0 < DD; k0 += 16) {
        bool more = (k0 + 16) < DD;
        float4 pa0 = make_float4(0.f,0.f,0.f,0.f), pa1 = pa0, pb0, pb1;
        if (more) {
            if (Arow) {
                pa0 = *(const float4*)(Arow + k0 + 16 + lc);
                pa1 = *(const float4*)(Arow + k0 + 16 + lc + 4);
                pa0.x *= sc; pa0.y *= sc; pa0.z *= sc; pa0.w *= sc;
                pa1.x *= sc; pa1.y *= sc; pa1.z *= sc; pa1.w *= sc;
            }
            pb0 = *(const float4*)(W + (size_t)(k0 + 16 + rb) * DD + cb);
            pb1 = *(const float4*)(W + (size_t)(k0 + 16 + rb) * DD + 64 + cb);
        }
#pragma unroll
        for (int kk = 0; kk < 16; kk++) {
            float4 a0 = *(float4*)&As[buf][kk][ty * 4];
            float4 a1 = *(float4*)&As[buf][kk][64 + ty * 4];
            // B fragments read as pre-packed 64-bit pairs (same bytes, zero pack cost)
            ulonglong2 bl = *(ulonglong2*)&Bs[buf][kk][tx * 4];
            ulonglong2 bh = *(ulonglong2*)&Bs[buf][kk][64 + tx * 4];
            u64 bb[4] = {bl.x, bl.y, bh.x, bh.y};
            float a[8] = {a0.x, a0.y, a0.z, a0.w, a1.x, a1.y, a1.z, a1.w};
#pragma unroll
            for (int i = 0; i < 8; i++) {
                u64 aa = splat2(a[i]);
                ffma2(acc[i][0], aa, bb[0]);
                ffma2(acc[i][1], aa, bb[1]);
                ffma2(acc[i][2], aa, bb[2]);
                ffma2(acc[i][3], aa, bb[3]);
            }
        }
        if (more) {
            int nb = buf ^ 1;
            As[nb][lc + 0][lr] = pa0.x; As[nb][lc + 1][lr] = pa0.y;
            As[nb][lc + 2][lr] = pa0.z; As[nb][lc + 3][lr] = pa0.w;
            As[nb][lc + 4][lr] = pa1.x; As[nb][lc + 5][lr] = pa1.y;
            As[nb][lc + 6][lr] = pa1.z; As[nb][lc + 7][lr] = pa1.w;
            *(float4*)&Bs[nb][rb][cb]      = pb0;
            *(float4*)&Bs[nb][rb][64 + cb] = pb1;
        }
        __syncthreads();
        buf ^= 1;
    }

    const float* bias = ga.bias[z] + (size_t)t * DD + blockIdx.y * 128;
    float4 bv0 = *(const float4*)(bias + tx * 4);
    float4 bv1 = *(const float4*)(bias + 64 + tx * 4);
    float* out = ga.out[z];
#pragma unroll
    for (int i = 0; i < 8; i++) {
        int rloc = (i < 4) ? (ty * 4 + i) : (64 + ty * 4 + i - 4);
        int nd = s_nodes[rloc];
        if (nd < 0) continue;
        float* o = out + (size_t)nd * DD + blockIdx.y * 128;
        float2 p0 = unpack2(acc[i][0]);
        float2 p1 = unpack2(acc[i][1]);
        float2 p2 = unpack2(acc[i][2]);
        float2 p3 = unpack2(acc[i][3]);
        float4 v0 = make_float4(p0.x + bv0.x, p0.y + bv0.y, p1.x + bv0.z, p1.y + bv0.w);
        float4 v1 = make_float4(p2.x + bv1.x, p2.y + bv1.y, p3.x + bv1.z, p3.y + bv1.w);
        *(float4*)(o + tx * 4)      = v0;
        *(float4*)(o + 64 + tx * 4) = v1;
    }
}

// ---------------- relation transforms: dst[r,node,h*64+e] = sum_d src[node,h*64+d] * W[r,h,d,e]
// Block = 256 nodes x one (phase,h). A tile staged transposed ONCE, reused across 6 relations.
// 8x8 micro-tile via packed f32x2 FMA.
__global__ __launch_bounds__(256) void rel_transform(const float* __restrict__ Watt,
                                                     const float* __restrict__ Wmsg,
                                                     int n) {
    extern __shared__ float sm[];
    float (*As)[264] = (float (*)[264])sm;             // [64][264] : [k][node]
    float (*Bs)[64]  = (float (*)[64])(sm + 64 * 264); // [64][64]  : [k][e]

    int tid = threadIdx.x;
    int z = blockIdx.z;              // 0..7
    int phase = z >> 2;
    int h = z & 3;

    const float* src   = phase ? g_v : g_k;
    const float* Wbase = phase ? Wmsg : Watt;
    float* dst         = phase ? g_vrel : g_krel;

    int row0 = blockIdx.x * 256;
    int tx = tid & 7, ty = tid >> 3;   // 8 cols x 32 row-groups

    // stage A transposed: thread tid owns node row0+tid (64 contiguous floats)
    {
        int node = row0 + tid;
        if (node < n) {
            const float* Arow = src + (size_t)node * DD + h * DKK;
#pragma unroll
            for (int i = 0; i < 16; i++) {
                float4 v = *(const float4*)(Arow + i * 4);
                As[i * 4 + 0][tid] = v.x;
                As[i * 4 + 1][tid] = v.y;
                As[i * 4 + 2][tid] = v.z;
                As[i * 4 + 3][tid] = v.w;
            }
        } else {
#pragma unroll
            for (int i = 0; i < 64; i++) As[i][tid] = 0.f;
        }
    }

    for (int r = 0; r < RR; r++) {
        __syncthreads();   // protect Bs overwrite (and A visibility on first iter)
        const float* Wp = Wbase + ((size_t)r * HH + h) * DKK * DKK;
        for (int i = tid; i < DKK * DKK / 4; i += 256)
            ((float4*)Bs)[i] = ((const float4*)Wp)[i];
        __syncthreads();

        u64 acc[8][4];
#pragma unroll
        for (int i = 0; i < 8; i++)
#pragma unroll
            for (int j = 0; j < 4; j++) acc[i][j] = 0ull;

#pragma unroll 16
        for (int kk = 0; kk < DKK; kk++) {
            float4 a0 = *(float4*)&As[kk][ty * 8];
            float4 a1 = *(float4*)&As[kk][ty * 8 + 4];
            ulonglong2 bl = *(ulonglong2*)&Bs[kk][tx * 8];
            ulonglong2 bh = *(ulonglong2*)&Bs[kk][tx * 8 + 4];
            u64 bb[4] = {bl.x, bl.y, bh.x, bh.y};
            float a[8] = {a0.x, a0.y, a0.z, a0.w, a1.x, a1.y, a1.z, a1.w};
#pragma unroll
            for (int i = 0; i < 8; i++) {
                u64 aa = splat2(a[i]);
                ffma2(acc[i][0], aa, bb[0]);
                ffma2(acc[i][1], aa, bb[1]);
                ffma2(acc[i][2], aa, bb[2]);
                ffma2(acc[i][3], aa, bb[3]);
            }
        }

#pragma unroll
        for (int i = 0; i < 8; i++) {
            int node = row0 + ty * 8 + i;
            if (node < n) {
                float* o = dst + ((size_t)r * n + node) * DD + h * DKK + tx * 8;
                float2 p0 = unpack2(acc[i][0]);
                float2 p1 = unpack2(acc[i][1]);
                float2 p2 = unpack2(acc[i][2]);
                float2 p3 = unpack2(acc[i][3]);
                *(float4*)o       = make_float4(p0.x, p0.y, p1.x, p1.y);
                *(float4*)(o + 4) = make_float4(p2.x, p2.y, p3.x, p3.y);
            }
        }
    }
}

// ---------------- edge pass 1: att -> exp, segment denom (softmax shift-invariant; max skipped)
__global__ void edge_att(const int* __restrict__ esrc, const int* __restrict__ edst,
                         const int* __restrict__ etype, const float* __restrict__ rel_pri,
                         int ne, int n) {
    int e = blockIdx.x * 8 + (threadIdx.x >> 5);
    if (e >= ne) return;
    int L = threadIdx.x & 31;
    int src = esrc[e], dst = edst[e], r = etype[e];

    const float4* qp = (const float4*)(g_q + (size_t)dst * DD) + L * 2;
    const float4* kp = (const float4*)(g_krel + ((size_t)r * n + src) * DD) + L * 2;
    float4 q0 = qp[0], q1 = qp[1];
    float4 k0 = kp[0], k1 = kp[1];
    float s = q0.x * k0.x + q0.y * k0.y + q0.z * k0.z + q0.w * k0.w
            + q1.x * k1.x + q1.y * k1.y + q1.z * k1.z + q1.w * k1.w;
    s += __shfl_xor_sync(0xffffffffu, s, 1);
    s += __shfl_xor_sync(0xffffffffu, s, 2);
    s += __shfl_xor_sync(0xffffffffu, s, 4);
    if ((L & 7) == 0) {
        int h = L >> 3;
        float att = s * rel_pri[r * HH + h] * 0.125f;   // 1/sqrt(64)
        float ex = expf(att);
        g_ex[(size_t)e * HH + h] = ex;
        atomicAdd(&g_denom[((size_t)dst * RR + r) * HH + h], ex);
    }
}

// ---------------- edge pass 2: t[dst] += w * v_rel[r,src]  (vectorized L2 reductions)
__global__ void edge_aggregate(const int* __restrict__ esrc, const int* __restrict__ edst,
                               const int* __restrict__ etype, int ne, int n) {
    int e = blockIdx.x * 8 + (threadIdx.x >> 5);
    if (e >= ne) return;
    int L = threadIdx.x & 31;
    int src = esrc[e], dst = edst[e], r = etype[e];
    int h = L >> 3;
    float w = g_ex[(size_t)e * HH + h] / g_denom[((size_t)dst * RR + r) * HH + h];

    const float4* vp = (const float4*)(g_vrel + ((size_t)r * n + src) * DD) + L * 2;
    float4 v0 = vp[0], v1 = vp[1];
    float* tp = g_t + (size_t)dst * DD + L * 8;
    asm volatile("red.global.add.v4.f32 [%0], {%1,%2,%3,%4};"
                 :: "l"(tp), "f"(v0.x * w), "f"(v0.y * w), "f"(v0.z * w), "f"(v0.w * w)
                 : "memory");
    asm volatile("red.global.add.v4.f32 [%0], {%1,%2,%3,%4};"
                 :: "l"(tp + 4), "f"(v1.x * w), "f"(v1.y * w), "f"(v1.z * w), "f"(v1.w * w)
                 : "memory");
}

// ---------------- per-node: relation count -> 1/nrel, has_msg
__global__ void node_nrel(int n) {
    int i = blockIdx.x * blockDim.x + threadIdx.x;
    if (i >= n) return;
    int c = 0;
#pragma unroll
    for (int r = 0; r < RR; r++)
        c += (g_denom[((size_t)i * RR + r) * HH] > 0.f) ? 1 : 0;
    g_hasmsg[i] = (c > 0) ? 1 : 0;
    g_invnrel[i] = 1.0f / (float)(c > 0 ? c : 1);
}

// ---------------- final: gated residual + layernorm + no-message passthrough (warp per node)
__global__ void finalize(const float* __restrict__ x, const float* __restrict__ skip,
                         const float* __restrict__ ln_g, const float* __restrict__ ln_b,
                         const int* __restrict__ nt, float* __restrict__ out, int n) {
    int node = blockIdx.x * 8 + (threadIdx.x >> 5);
    if (node >= n) return;
    int L = threadIdx.x & 31;
    int t = nt[node];
    float alpha = 1.0f / (1.0f + expf(-skip[t]));
    float beta = 1.0f - alpha;

    const float4* xp = (const float4*)(x + (size_t)node * DD) + L * 2;
    const float4* tp = (const float4*)(g_trans + (size_t)node * DD) + L * 2;
    float4 x0 = xp[0], x1 = xp[1];
    float4 t0 = tp[0], t1 = tp[1];

    float o[8];
    o[0] = t0.x * alpha + x0.x * beta;
    o[1] = t0.y * alpha + x0.y * beta;
    o[2] = t0.z * alpha + x0.z * beta;
    o[3] = t0.w * alpha + x0.w * beta;
    o[4] = t1.x * alpha + x1.x * beta;
    o[5] = t1.y * alpha + x1.y * beta;
    o[6] = t1.z * alpha + x1.z * beta;
    o[7] = t1.w * alpha + x1.w * beta;

    float s = 0.f, s2 = 0.f;
#pragma unroll
    for (int j = 0; j < 8; j++) { s += o[j]; s2 += o[j] * o[j]; }
#pragma unroll
    for (int off = 16; off > 0; off >>= 1) {
        s  += __shfl_xor_sync(0xffffffffu, s, off);
        s2 += __shfl_xor_sync(0xffffffffu, s2, off);
    }
    float mu = s * (1.0f / DD);
    float var = s2 * (1.0f / DD) - mu * mu;
    float rstd = rsqrtf(var + 1e-5f);

    float4 r0, r1;
    if (g_hasmsg[node]) {
        const float4* gp = (const float4*)(ln_g + (size_t)t * DD) + L * 2;
        const float4* bp = (const float4*)(ln_b + (size_t)t * DD) + L * 2;
        float4 g0 = gp[0], g1 = gp[1];
        float4 b0 = bp[0], b1 = bp[1];
        r0.x = (o[0] - mu) * rstd * g0.x + b0.x;
        r0.y = (o[1] - mu) * rstd * g0.y + b0.y;
        r0.z = (o[2] - mu) * rstd * g0.z + b0.z;
        r0.w = (o[3] - mu) * rstd * g0.w + b0.w;
        r1.x = (o[4] - mu) * rstd * g1.x + b1.x;
        r1.y = (o[5] - mu) * rstd * g1.y + b1.y;
        r1.z = (o[6] - mu) * rstd * g1.z + b1.z;
        r1.w = (o[7] - mu) * rstd * g1.w + b1.w;
    } else {
        r0 = x0; r1 = x1;
    }
    float4* op = (float4*)(out + (size_t)node * DD) + L * 2;
    op[0] = r0;
    op[1] = r1;
}

// ---------------- host launcher ----------------
extern "C" void kernel_launch(void* const* d_in, const int* in_sizes, int n_in,
                              void* d_out, int out_size) {
    const float* x       = (const float*)d_in[0];
    const float* Wk      = (const float*)d_in[1];
    const float* bk      = (const float*)d_in[2];
    const float* Wq      = (const float*)d_in[3];
    const float* bq      = (const float*)d_in[4];
    const float* Wv      = (const float*)d_in[5];
    const float* bv      = (const float*)d_in[6];
    const float* Wa      = (const float*)d_in[7];
    const float* ba      = (const float*)d_in[8];
    const float* rel_pri = (const float*)d_in[9];
    const float* rel_att = (const float*)d_in[10];
    const float* rel_msg = (const float*)d_in[11];
    const float* skip    = (const float*)d_in[12];
    const float* ln_g    = (const float*)d_in[13];
    const float* ln_b    = (const float*)d_in[14];
    const int* node_type = (const int*)d_in[15];
    const int* edge_src  = (const int*)d_in[16];
    const int* edge_dst  = (const int*)d_in[17];
    const int* edge_type = (const int*)d_in[18];

    int n  = in_sizes[0] / DD;
    int ne = in_sizes[16];
    if (n > NN || ne > EE) return;  // sized for the benchmark shapes

    void *p_cnt, *p_cursor, *p_perm, *p_denom, *p_t;
    void *p_k, *p_q, *p_v, *p_trans, *p_invnrel;
    cudaGetSymbolAddress(&p_cnt, g_cnt);
    cudaGetSymbolAddress(&p_cursor, g_cursor);
    cudaGetSymbolAddress(&p_perm, g_perm);
    cudaGetSymbolAddress(&p_denom, g_denom);
    cudaGetSymbolAddress(&p_t, g_t);
    cudaGetSymbolAddress(&p_k, g_k);
    cudaGetSymbolAddress(&p_q, g_q);
    cudaGetSymbolAddress(&p_v, g_v);
    cudaGetSymbolAddress(&p_trans, g_trans);
    cudaGetSymbolAddress(&p_invnrel, g_invnrel);

    cudaMemsetAsync(p_cnt, 0, sizeof(int) * TT);
    cudaMemsetAsync(p_cursor, 0, sizeof(int) * TT);
    cudaMemsetAsync(p_perm, 0xFF, sizeof(int) * NPADMAX);
    cudaMemsetAsync(p_denom, 0, sizeof(float) * (size_t)n * RR * HH);
    cudaMemsetAsync(p_t, 0, sizeof(float) * (size_t)n * DD);

    // type bucketing
    count_types<<<(n + 255) / 256, 256>>>(node_type, n);
    make_offsets<<<1, 1>>>();
    scatter_perm<<<(n + 255) / 256, 256>>>(node_type, n);

    // fused KQV typed linears (grid.z = {k,q,v})
    GemmArgs g1;
    g1.A = x; g1.scale = nullptr;
    g1.W[0] = Wk; g1.W[1] = Wq; g1.W[2] = Wv;
    g1.bias[0] = bk; g1.bias[1] = bq; g1.bias[2] = bv;
    g1.out[0] = (float*)p_k; g1.out[1] = (float*)p_q; g1.out[2] = (float*)p_v;
    dim3 grid1((n + 127) / 128 + TT, DD / 128, 3);
    typed_gemm<<<grid1, 256>>>(g1);

    // relation transforms: batched GEMM, A-tile reused across all 6 relations
    int relSmem = (64 * 264 + 64 * 64) * sizeof(float);   // ~84KB
    cudaFuncSetAttribute(rel_transform, cudaFuncAttributeMaxDynamicSharedMemorySize, relSmem);
    dim3 gridR((n + 255) / 256, 1, 2 * HH);
    rel_transform<<<gridR, 256, relSmem>>>(rel_att, rel_msg, n);

    // edge passes
    edge_att<<<(ne + 7) / 8, 256>>>(edge_src, edge_dst, edge_type, rel_pri, ne, n);
    edge_aggregate<<<(ne + 7) / 8, 256>>>(edge_src, edge_dst, edge_type, ne, n);
    node_nrel<<<(n + 255) / 256, 256>>>(n);

    // output typed linear (with 1/nrel row scaling)
    GemmArgs g2;
    g2.A = (const float*)p_t; g2.scale = (const float*)p_invnrel;
    g2.W[0] = Wa; g2.W[1] = Wa; g2.W[2] = Wa;
    g2.bias[0] = ba; g2.bias[1] = ba; g2.bias[2] = ba;
    g2.out[0] = (float*)p_trans; g2.out[1] = (float*)p_trans; g2.out[2] = (float*)p_trans;
    dim3 grid2((n + 127) / 128 + TT, DD / 128, 1);
    typed_gemm<<<grid2, 256>>>(g2);

    // gated residual + LN + passthrough
    finalize<<<(n + 7) / 8, 256>>>(x, skip, ln_g, ln_b, node_type, (float*)d_out, n);
}

// round 8
// speedup vs baseline: 1.6222x; 1.0784x over previous
#include <cuda_runtime.h>
#include <cuda_bf16.h>
#include <math.h>
#include <stdint.h>

#define TT 3
#define RR 6
#define HH 4
#define DKK 64
#define DD 256
#define NN 50000
#define EE 400000
#define NPADMAX (NN + TT * 128)

typedef unsigned long long u64;

// ---- packed f32x2 helpers (for rel_transform) ----
__device__ __forceinline__ u64 splat2(float x) {
    u64 r;
    asm("mov.b64 %0, {%1, %1};" : "=l"(r) : "r"(__float_as_uint(x)));
    return r;
}
__device__ __forceinline__ void ffma2(u64& d, u64 a, u64 b) {
    asm("fma.rn.f32x2 %0, %1, %2, %3;" : "=l"(d) : "l"(a), "l"(b), "l"(d));
}
__device__ __forceinline__ float2 unpack2(u64 v) {
    unsigned int lo, hi;
    asm("mov.b64 {%0, %1}, %2;" : "=r"(lo), "=r"(hi) : "l"(v));
    return make_float2(__uint_as_float(lo), __uint_as_float(hi));
}

// ---- mma.sync / ldmatrix / cp.async helpers (sm_80-era, legal on sm_103) ----
__device__ __forceinline__ uint32_t smem_to_u32(const void* p) {
    uint32_t a;
    asm("{ .reg .u64 t; cvta.to.shared.u64 t, %1; cvt.u32.u64 %0, t; }" : "=r"(a) : "l"(p));
    return a;
}
__device__ __forceinline__ void ldsm4(uint32_t r[4], uint32_t addr) {
    asm volatile("ldmatrix.sync.aligned.m8n8.x4.shared.b16 {%0,%1,%2,%3}, [%4];"
        : "=r"(r[0]), "=r"(r[1]), "=r"(r[2]), "=r"(r[3]) : "r"(addr));
}
__device__ __forceinline__ void mma16816(float d[4], const uint32_t a[4], uint32_t b0, uint32_t b1) {
    asm volatile("mma.sync.aligned.m16n8k16.row.col.f32.bf16.bf16.f32 "
        "{%0,%1,%2,%3}, {%4,%5,%6,%7}, {%8,%9}, {%0,%1,%2,%3};"
        : "+f"(d[0]), "+f"(d[1]), "+f"(d[2]), "+f"(d[3])
        : "r"(a[0]), "r"(a[1]), "r"(a[2]), "r"(a[3]), "r"(b0), "r"(b1));
}
__device__ __forceinline__ void cp_async16(uint32_t dst, const void* src, bool valid) {
    int sz = valid ? 16 : 0;
    asm volatile("cp.async.cg.shared.global [%0], [%1], 16, %2;"
                 :: "r"(dst), "l"(src), "r"(sz));
}
#define CP_COMMIT() asm volatile("cp.async.commit_group;" ::: "memory")
#define CP_WAIT1()  asm volatile("cp.async.wait_group 1;" ::: "memory")
#define CP_WAIT0()  asm volatile("cp.async.wait_group 0;" ::: "memory")

// ---------------- scratch (device globals) ----------------
__device__ float g_k[(size_t)NN * DD];
__device__ float g_q[(size_t)NN * DD];
__device__ float g_v[(size_t)NN * DD];
__device__ float g_t[(size_t)NN * DD];
__device__ float g_trans[(size_t)NN * DD];
__device__ float g_krel[(size_t)RR * NN * DD];
__device__ float g_vrel[(size_t)RR * NN * DD];
__device__ float g_ex[(size_t)EE * HH];
__device__ float g_denom[(size_t)NN * RR * HH];
__device__ float g_invnrel[NN];
__device__ int   g_hasmsg[NN];
__device__ int   g_perm[NPADMAX];
__device__ int   g_cnt[TT];
__device__ int   g_cursor[TT];
__device__ int   g_padoff[TT + 1];
// bf16 hi/lo split buffers
__device__ __nv_bfloat16 g_xhi[(size_t)NN * DD];
__device__ __nv_bfloat16 g_xlo[(size_t)NN * DD];
__device__ __nv_bfloat16 g_thi[(size_t)NN * DD];
__device__ __nv_bfloat16 g_tlo[(size_t)NN * DD];
__device__ __nv_bfloat16 g_whiT[(size_t)4 * TT * DD * DD];   // [mat][t][j][k]  (W transposed)
__device__ __nv_bfloat16 g_wloT[(size_t)4 * TT * DD * DD];

// ---------------- type bucketing ----------------
__global__ void count_types(const int* __restrict__ nt, int n) {
    int i = blockIdx.x * blockDim.x + threadIdx.x;
    if (i < n) atomicAdd(&g_cnt[nt[i]], 1);
}
__global__ void make_offsets() {
    if (threadIdx.x == 0 && blockIdx.x == 0) {
        int off = 0;
        for (int t = 0; t < TT; t++) {
            g_padoff[t] = off;
            off += ((g_cnt[t] + 127) >> 7) << 7;
        }
        g_padoff[TT] = off;
    }
}
__global__ void scatter_perm(const int* __restrict__ nt, int n) {
    int i = blockIdx.x * blockDim.x + threadIdx.x;
    if (i < n) {
        int t = nt[i];
        int pos = g_padoff[t] + atomicAdd(&g_cursor[t], 1);
        g_perm[pos] = i;
    }
}

// ---------------- bf16 hi/lo split conversions ----------------
__global__ void conv_split(const float* __restrict__ src, const float* __restrict__ scale,
                           __nv_bfloat16* __restrict__ hi, __nv_bfloat16* __restrict__ lo, int n) {
    size_t i = (size_t)blockIdx.x * blockDim.x + threadIdx.x;
    if (i >= (size_t)n * 128) return;
    int node = (int)(i >> 7);
    float s = scale ? scale[node] : 1.0f;
    float2 f = ((const float2*)src)[i];
    f.x *= s; f.y *= s;
    __nv_bfloat16 h0 = __float2bfloat16(f.x);
    __nv_bfloat16 h1 = __float2bfloat16(f.y);
    __nv_bfloat16 l0 = __float2bfloat16(f.x - __bfloat162float(h0));
    __nv_bfloat16 l1 = __float2bfloat16(f.y - __bfloat162float(h1));
    hi[i * 2] = h0; hi[i * 2 + 1] = h1;
    lo[i * 2] = l0; lo[i * 2 + 1] = l1;
}

__global__ void conv_w(const float* __restrict__ Wk, const float* __restrict__ Wq,
                       const float* __restrict__ Wv, const float* __restrict__ Wa) {
    size_t i = (size_t)blockIdx.x * blockDim.x + threadIdx.x;
    if (i >= (size_t)4 * TT * DD * DD) return;
    int j = (int)(i % DD);
    size_t r = i / DD;
    int k = (int)(r % DD); r /= DD;
    int t = (int)(r % TT);
    int mat = (int)(r / TT);
    const float* src = (mat == 0) ? Wk : (mat == 1) ? Wq : (mat == 2) ? Wv : Wa;
    float w = src[((size_t)t * DD + k) * DD + j];
    __nv_bfloat16 h = __float2bfloat16(w);
    __nv_bfloat16 l = __float2bfloat16(w - __bfloat162float(h));
    size_t di = (((size_t)mat * TT + t) * DD + j) * DD + k;   // transposed [j][k]
    g_whiT[di] = h;
    g_wloT[di] = l;
}

// ---------------- tensor-core typed linear (mma.sync bf16x3 split precision)
// out[n] = A[n] @ W[type(n)] + bias[type(n)];  D = Ahi*Bhi + Ahi*Blo + Alo*Bhi (fp32 acc).
// BM=128, BN=128, BK=32, 8 warps (4M x 2N), warp tile 32x64, cp.async double-buffered.
struct TcArgs {
    const __nv_bfloat16* Ahi;      // [n][256]
    const __nv_bfloat16* Alo;
    const __nv_bfloat16* WhiT[3];  // [t][j][k]
    const __nv_bfloat16* WloT[3];
    const float* bias[3];
    float*       out[3];
};

// smem layout per buffer (48KB): A at 0, B at 24KB.
//   tile(split, kstep, row, kcol): split*12288 + kstep*6144 + row*48 + kcol*2  bytes
//   (row pad 24 bf16 = 48B -> ldmatrix conflict-free: r*48 mod 128 distinct for 8 rows)
#define STG_BUF   49152
#define STG_BOFF  24576
#define STG_SPLIT 12288
#define STG_KST   6144
#define ROWB      48

__global__ __launch_bounds__(256) void typed_gemm_tc(TcArgs args) {
    extern __shared__ char smem[];
    __shared__ int s_nodes[128];

    int row0 = blockIdx.x * 128;
    if (row0 >= g_padoff[TT]) return;
    int t = 0;
#pragma unroll
    for (int tt = 0; tt < TT - 1; tt++)
        if (row0 >= g_padoff[tt + 1]) t = tt + 1;

    uint32_t smem_base = smem_to_u32(smem);
    int tid = threadIdx.x;
    int lane = tid & 31;
    int wid = tid >> 5;
    int wy = wid & 3, wx = wid >> 2;

    if (tid < 128) s_nodes[tid] = g_perm[row0 + tid];
    __syncthreads();

    int z = blockIdx.z;
    int y0 = blockIdx.y * 128;
    const __nv_bfloat16* WhiT = args.WhiT[z] + ((size_t)t * DD + y0) * DD;
    const __nv_bfloat16* WloT = args.WloT[z] + ((size_t)t * DD + y0) * DD;

    // staging: slot s in [0,512): row=s>>2, kstep=(s>>1)&1, u4=s&1 -> 16B each
    int srow = tid >> 1;             // thread's two slots share row? no: use slot = tid + i*256
    (void)srow;
    int nodeCache[2];
    {
        int s0 = tid, s1 = tid + 256;
        nodeCache[0] = s_nodes[s0 >> 2];
        nodeCache[1] = s_nodes[s1 >> 2];
    }

    auto stage = [&](int chunk, int buf) {
        uint32_t sb = smem_base + buf * STG_BUF;
        int k0 = chunk * 32;
#pragma unroll
        for (int i = 0; i < 2; i++) {
            int slot = tid + i * 256;
            int row = slot >> 2, kstep = (slot >> 1) & 1, u4 = slot & 1;
            int node = nodeCache[i];
            int ksub = k0 + kstep * 16 + u4 * 8;
            uint32_t dA = sb + kstep * STG_KST + row * ROWB + u4 * 16;
            const __nv_bfloat16* pa = args.Ahi + ((size_t)(node < 0 ? 0 : node) * DD + ksub);
            const __nv_bfloat16* pl = args.Alo + ((size_t)(node < 0 ? 0 : node) * DD + ksub);
            cp_async16(dA, pa, node >= 0);
            cp_async16(dA + STG_SPLIT, pl, node >= 0);
            uint32_t dB = sb + STG_BOFF + kstep * STG_KST + row * ROWB + u4 * 16;
            cp_async16(dB, WhiT + (size_t)row * DD + ksub, true);
            cp_async16(dB + STG_SPLIT, WloT + (size_t)row * DD + ksub, true);
        }
    };

    float acc[2][8][4];
#pragma unroll
    for (int a = 0; a < 2; a++)
#pragma unroll
        for (int b = 0; b < 8; b++)
#pragma unroll
            for (int c = 0; c < 4; c++) acc[a][b][c] = 0.f;

    stage(0, 0);
    CP_COMMIT();

    // ldmatrix lane addressing
    int rsel = (lane & 7) + ((lane >> 3) & 1) * 8;
    int kc2 = ((lane >> 4) & 1) * 16;   // byte offset of k-col (8 bf16)

    int buf = 0;
    for (int c = 0; c < 8; c++) {
        if (c < 7) { stage(c + 1, buf ^ 1); CP_COMMIT(); }
        if (c < 7) CP_WAIT1(); else CP_WAIT0();
        __syncthreads();

        uint32_t sb = smem_base + buf * STG_BUF;
#pragma unroll
        for (int kstep = 0; kstep < 2; kstep++) {
            uint32_t ah[2][4], al[2][4], bh[4][4], bl[4][4];
            uint32_t baseA = sb + kstep * STG_KST;
            uint32_t baseB = sb + STG_BOFF + kstep * STG_KST;
#pragma unroll
            for (int mf = 0; mf < 2; mf++) {
                uint32_t ad = baseA + (uint32_t)((wy * 32 + mf * 16 + rsel) * ROWB) + kc2;
                ldsm4(ah[mf], ad);
                ldsm4(al[mf], ad + STG_SPLIT);
            }
#pragma unroll
            for (int p = 0; p < 4; p++) {
                uint32_t bd = baseB + (uint32_t)((wx * 64 + p * 16 + rsel) * ROWB) + kc2;
                ldsm4(bh[p], bd);
                ldsm4(bl[p], bd + STG_SPLIT);
            }
#pragma unroll
            for (int mf = 0; mf < 2; mf++)
#pragma unroll
                for (int p = 0; p < 4; p++)
#pragma unroll
                    for (int half = 0; half < 2; half++) {
                        float* d = acc[mf][p * 2 + half];
                        mma16816(d, ah[mf], bh[p][half], bh[p][2 + half]);
                        mma16816(d, ah[mf], bl[p][half], bl[p][2 + half]);
                        mma16816(d, al[mf], bh[p][half], bh[p][2 + half]);
                    }
        }
        __syncthreads();
        buf ^= 1;
    }

    // epilogue: fragment-direct scatter with bias
    const float* bias = args.bias[z] + (size_t)t * DD + y0;
    float* out = args.out[z];
#pragma unroll
    for (int mf = 0; mf < 2; mf++) {
        int mr = wy * 32 + mf * 16 + (lane >> 2);
        int nd0 = s_nodes[mr];
        int nd1 = s_nodes[mr + 8];
        float* o0 = (nd0 >= 0) ? (out + (size_t)nd0 * DD + y0) : nullptr;
        float* o1 = (nd1 >= 0) ? (out + (size_t)nd1 * DD + y0) : nullptr;
#pragma unroll
        for (int nf = 0; nf < 8; nf++) {
            int col = wx * 64 + nf * 8 + (lane & 3) * 2;
            float bx = bias[col], by = bias[col + 1];
            if (o0) *(float2*)(o0 + col) = make_float2(acc[mf][nf][0] + bx, acc[mf][nf][1] + by);
            if (o1) *(float2*)(o1 + col) = make_float2(acc[mf][nf][2] + bx, acc[mf][nf][3] + by);
        }
    }
}

// ---------------- relation transforms (FFMA2 GEMM, A-tile reused across relations) ------
__global__ __launch_bounds__(256) void rel_transform(const float* __restrict__ Watt,
                                                     const float* __restrict__ Wmsg,
                                                     int n) {
    extern __shared__ float sm[];
    float (*As)[264] = (float (*)[264])sm;
    float (*Bs)[64]  = (float (*)[64])(sm + 64 * 264);

    int tid = threadIdx.x;
    int z = blockIdx.z;
    int phase = z >> 2;
    int h = z & 3;

    const float* src   = phase ? g_v : g_k;
    const float* Wbase = phase ? Wmsg : Watt;
    float* dst         = phase ? g_vrel : g_krel;

    int row0 = blockIdx.x * 256;
    int tx = tid & 7, ty = tid >> 3;

    {
        int node = row0 + tid;
        if (node < n) {
            const float* Arow = src + (size_t)node * DD + h * DKK;
#pragma unroll
            for (int i = 0; i < 16; i++) {
                float4 v = *(const float4*)(Arow + i * 4);
                As[i * 4 + 0][tid] = v.x;
                As[i * 4 + 1][tid] = v.y;
                As[i * 4 + 2][tid] = v.z;
                As[i * 4 + 3][tid] = v.w;
            }
        } else {
#pragma unroll
            for (int i = 0; i < 64; i++) As[i][tid] = 0.f;
        }
    }

    for (int r = 0; r < RR; r++) {
        __syncthreads();
        const float* Wp = Wbase + ((size_t)r * HH + h) * DKK * DKK;
        for (int i = tid; i < DKK * DKK / 4; i += 256)
            ((float4*)Bs)[i] = ((const float4*)Wp)[i];
        __syncthreads();

        u64 acc[8][4];
#pragma unroll
        for (int i = 0; i < 8; i++)
#pragma unroll
            for (int j = 0; j < 4; j++) acc[i][j] = 0ull;

#pragma unroll 16
        for (int kk = 0; kk < DKK; kk++) {
            float4 a0 = *(float4*)&As[kk][ty * 8];
            float4 a1 = *(float4*)&As[kk][ty * 8 + 4];
            ulonglong2 blv = *(ulonglong2*)&Bs[kk][tx * 8];
            ulonglong2 bhv = *(ulonglong2*)&Bs[kk][tx * 8 + 4];
            u64 bb[4] = {blv.x, blv.y, bhv.x, bhv.y};
            float a[8] = {a0.x, a0.y, a0.z, a0.w, a1.x, a1.y, a1.z, a1.w};
#pragma unroll
            for (int i = 0; i < 8; i++) {
                u64 aa = splat2(a[i]);
                ffma2(acc[i][0], aa, bb[0]);
                ffma2(acc[i][1], aa, bb[1]);
                ffma2(acc[i][2], aa, bb[2]);
                ffma2(acc[i][3], aa, bb[3]);
            }
        }

#pragma unroll
        for (int i = 0; i < 8; i++) {
            int node = row0 + ty * 8 + i;
            if (node < n) {
                float* o = dst + ((size_t)r * n + node) * DD + h * DKK + tx * 8;
                float2 p0 = unpack2(acc[i][0]);
                float2 p1 = unpack2(acc[i][1]);
                float2 p2 = unpack2(acc[i][2]);
                float2 p3 = unpack2(acc[i][3]);
                *(float4*)o       = make_float4(p0.x, p0.y, p1.x, p1.y);
                *(float4*)(o + 4) = make_float4(p2.x, p2.y, p3.x, p3.y);
            }
        }
    }
}

// ---------------- edge pass 1 ----------------
__global__ void edge_att(const int* __restrict__ esrc, const int* __restrict__ edst,
                         const int* __restrict__ etype, const float* __restrict__ rel_pri,
                         int ne, int n) {
    int e = blockIdx.x * 8 + (threadIdx.x >> 5);
    if (e >= ne) return;
    int L = threadIdx.x & 31;
    int src = esrc[e], dst = edst[e], r = etype[e];

    const float4* qp = (const float4*)(g_q + (size_t)dst * DD) + L * 2;
    const float4* kp = (const float4*)(g_krel + ((size_t)r * n + src) * DD) + L * 2;
    float4 q0 = qp[0], q1 = qp[1];
    float4 k0 = kp[0], k1 = kp[1];
    float s = q0.x * k0.x + q0.y * k0.y + q0.z * k0.z + q0.w * k0.w
            + q1.x * k1.x + q1.y * k1.y + q1.z * k1.z + q1.w * k1.w;
    s += __shfl_xor_sync(0xffffffffu, s, 1);
    s += __shfl_xor_sync(0xffffffffu, s, 2);
    s += __shfl_xor_sync(0xffffffffu, s, 4);
    if ((L & 7) == 0) {
        int h = L >> 3;
        float att = s * rel_pri[r * HH + h] * 0.125f;
        float ex = expf(att);
        g_ex[(size_t)e * HH + h] = ex;
        atomicAdd(&g_denom[((size_t)dst * RR + r) * HH + h], ex);
    }
}

// ---------------- edge pass 2 ----------------
__global__ void edge_aggregate(const int* __restrict__ esrc, const int* __restrict__ edst,
                               const int* __restrict__ etype, int ne, int n) {
    int e = blockIdx.x * 8 + (threadIdx.x >> 5);
    if (e >= ne) return;
    int L = threadIdx.x & 31;
    int src = esrc[e], dst = edst[e], r = etype[e];
    int h = L >> 3;
    float w = g_ex[(size_t)e * HH + h] / g_denom[((size_t)dst * RR + r) * HH + h];

    const float4* vp = (const float4*)(g_vrel + ((size_t)r * n + src) * DD) + L * 2;
    float4 v0 = vp[0], v1 = vp[1];
    float* tp = g_t + (size_t)dst * DD + L * 8;
    asm volatile("red.global.add.v4.f32 [%0], {%1,%2,%3,%4};"
                 :: "l"(tp), "f"(v0.x * w), "f"(v0.y * w), "f"(v0.z * w), "f"(v0.w * w)
                 : "memory");
    asm volatile("red.global.add.v4.f32 [%0], {%1,%2,%3,%4};"
                 :: "l"(tp + 4), "f"(v1.x * w), "f"(v1.y * w), "f"(v1.z * w), "f"(v1.w * w)
                 : "memory");
}

// ---------------- per-node nrel ----------------
__global__ void node_nrel(int n) {
    int i = blockIdx.x * blockDim.x + threadIdx.x;
    if (i >= n) return;
    int c = 0;
#pragma unroll
    for (int r = 0; r < RR; r++)
        c += (g_denom[((size_t)i * RR + r) * HH] > 0.f) ? 1 : 0;
    g_hasmsg[i] = (c > 0) ? 1 : 0;
    g_invnrel[i] = 1.0f / (float)(c > 0 ? c : 1);
}

// ---------------- final: gated residual + LN + passthrough ----------------
__global__ void finalize(const float* __restrict__ x, const float* __restrict__ skip,
                         const float* __restrict__ ln_g, const float* __restrict__ ln_b,
                         const int* __restrict__ nt, float* __restrict__ out, int n) {
    int node = blockIdx.x * 8 + (threadIdx.x >> 5);
    if (node >= n) return;
    int L = threadIdx.x & 31;
    int t = nt[node];
    float alpha = 1.0f / (1.0f + expf(-skip[t]));
    float beta = 1.0f - alpha;

    const float4* xp = (const float4*)(x + (size_t)node * DD) + L * 2;
    const float4* tp = (const float4*)(g_trans + (size_t)node * DD) + L * 2;
    float4 x0 = xp[0], x1 = xp[1];
    float4 t0 = tp[0], t1 = tp[1];

    float o[8];
    o[0] = t0.x * alpha + x0.x * beta;
    o[1] = t0.y * alpha + x0.y * beta;
    o[2] = t0.z * alpha + x0.z * beta;
    o[3] = t0.w * alpha + x0.w * beta;
    o[4] = t1.x * alpha + x1.x * beta;
    o[5] = t1.y * alpha + x1.y * beta;
    o[6] = t1.z * alpha + x1.z * beta;
    o[7] = t1.w * alpha + x1.w * beta;

    float s = 0.f, s2 = 0.f;
#pragma unroll
    for (int j = 0; j < 8; j++) { s += o[j]; s2 += o[j] * o[j]; }
#pragma unroll
    for (int off = 16; off > 0; off >>= 1) {
        s  += __shfl_xor_sync(0xffffffffu, s, off);
        s2 += __shfl_xor_sync(0xffffffffu, s2, off);
    }
    float mu = s * (1.0f / DD);
    float var = s2 * (1.0f / DD) - mu * mu;
    float rstd = rsqrtf(var + 1e-5f);

    float4 r0, r1;
    if (g_hasmsg[node]) {
        const float4* gp = (const float4*)(ln_g + (size_t)t * DD) + L * 2;
        const float4* bp = (const float4*)(ln_b + (size_t)t * DD) + L * 2;
        float4 g0 = gp[0], g1 = gp[1];
        float4 b0 = bp[0], b1 = bp[1];
        r0.x = (o[0] - mu) * rstd * g0.x + b0.x;
        r0.y = (o[1] - mu) * rstd * g0.y + b0.y;
        r0.z = (o[2] - mu) * rstd * g0.z + b0.z;
        r0.w = (o[3] - mu) * rstd * g0.w + b0.w;
        r1.x = (o[4] - mu) * rstd * g1.x + b1.x;
        r1.y = (o[5] - mu) * rstd * g1.y + b1.y;
        r1.z = (o[6] - mu) * rstd * g1.z + b1.z;
        r1.w = (o[7] - mu) * rstd * g1.w + b1.w;
    } else {
        r0 = x0; r1 = x1;
    }
    float4* op = (float4*)(out + (size_t)node * DD) + L * 2;
    op[0] = r0;
    op[1] = r1;
}

// ---------------- host launcher ----------------
extern "C" void kernel_launch(void* const* d_in, const int* in_sizes, int n_in,
                              void* d_out, int out_size) {
    const float* x       = (const float*)d_in[0];
    const float* Wk      = (const float*)d_in[1];
    const float* bk      = (const float*)d_in[2];
    const float* Wq      = (const float*)d_in[3];
    const float* bq      = (const float*)d_in[4];
    const float* Wv      = (const float*)d_in[5];
    const float* bv      = (const float*)d_in[6];
    const float* Wa      = (const float*)d_in[7];
    const float* ba      = (const float*)d_in[8];
    const float* rel_pri = (const float*)d_in[9];
    const float* rel_att = (const float*)d_in[10];
    const float* rel_msg = (const float*)d_in[11];
    const float* skip    = (const float*)d_in[12];
    const float* ln_g    = (const float*)d_in[13];
    const float* ln_b    = (const float*)d_in[14];
    const int* node_type = (const int*)d_in[15];
    const int* edge_src  = (const int*)d_in[16];
    const int* edge_dst  = (const int*)d_in[17];
    const int* edge_type = (const int*)d_in[18];

    int n  = in_sizes[0] / DD;
    int ne = in_sizes[16];
    if (n > NN || ne > EE) return;

    void *p_cnt, *p_cursor, *p_perm, *p_denom, *p_t;
    void *p_k, *p_q, *p_v, *p_trans, *p_invnrel;
    void *p_xhi, *p_xlo, *p_thi, *p_tlo, *p_whiT, *p_wloT;
    cudaGetSymbolAddress(&p_cnt, g_cnt);
    cudaGetSymbolAddress(&p_cursor, g_cursor);
    cudaGetSymbolAddress(&p_perm, g_perm);
    cudaGetSymbolAddress(&p_denom, g_denom);
    cudaGetSymbolAddress(&p_t, g_t);
    cudaGetSymbolAddress(&p_k, g_k);
    cudaGetSymbolAddress(&p_q, g_q);
    cudaGetSymbolAddress(&p_v, g_v);
    cudaGetSymbolAddress(&p_trans, g_trans);
    cudaGetSymbolAddress(&p_invnrel, g_invnrel);
    cudaGetSymbolAddress(&p_xhi, g_xhi);
    cudaGetSymbolAddress(&p_xlo, g_xlo);
    cudaGetSymbolAddress(&p_thi, g_thi);
    cudaGetSymbolAddress(&p_tlo, g_tlo);
    cudaGetSymbolAddress(&p_whiT, g_whiT);
    cudaGetSymbolAddress(&p_wloT, g_wloT);

    cudaMemsetAsync(p_cnt, 0, sizeof(int) * TT);
    cudaMemsetAsync(p_cursor, 0, sizeof(int) * TT);
    cudaMemsetAsync(p_perm, 0xFF, sizeof(int) * NPADMAX);
    cudaMemsetAsync(p_denom, 0, sizeof(float) * (size_t)n * RR * HH);
    cudaMemsetAsync(p_t, 0, sizeof(float) * (size_t)n * DD);

    // conversions + bucketing
    conv_w<<<(4 * TT * DD * DD + 255) / 256, 256>>>(Wk, Wq, Wv, Wa);
    conv_split<<<(int)(((size_t)n * 128 + 255) / 256), 256>>>(x, nullptr,
        (__nv_bfloat16*)p_xhi, (__nv_bfloat16*)p_xlo, n);
    count_types<<<(n + 255) / 256, 256>>>(node_type, n);
    make_offsets<<<1, 1>>>();
    scatter_perm<<<(n + 255) / 256, 256>>>(node_type, n);

    cudaFuncSetAttribute(typed_gemm_tc, cudaFuncAttributeMaxDynamicSharedMemorySize, 2 * STG_BUF);

    // fused KQV typed linears on tensor cores (mma.sync)
    TcArgs a1;
    a1.Ahi = (const __nv_bfloat16*)p_xhi;
    a1.Alo = (const __nv_bfloat16*)p_xlo;
    for (int m = 0; m < 3; m++) {
        a1.WhiT[m] = (const __nv_bfloat16*)p_whiT + (size_t)m * TT * DD * DD;
        a1.WloT[m] = (const __nv_bfloat16*)p_wloT + (size_t)m * TT * DD * DD;
    }
    a1.bias[0] = bk; a1.bias[1] = bq; a1.bias[2] = bv;
    a1.out[0] = (float*)p_k; a1.out[1] = (float*)p_q; a1.out[2] = (float*)p_v;
    dim3 grid1((n + 127) / 128 + TT, DD / 128, 3);
    typed_gemm_tc<<<grid1, 256, 2 * STG_BUF>>>(a1);

    // relation transforms
    int relSmem = (64 * 264 + 64 * 64) * sizeof(float);
    cudaFuncSetAttribute(rel_transform, cudaFuncAttributeMaxDynamicSharedMemorySize, relSmem);
    dim3 gridR((n + 255) / 256, 1, 2 * HH);
    rel_transform<<<gridR, 256, relSmem>>>(rel_att, rel_msg, n);

    // edge passes
    edge_att<<<(ne + 7) / 8, 256>>>(edge_src, edge_dst, edge_type, rel_pri, ne, n);
    edge_aggregate<<<(ne + 7) / 8, 256>>>(edge_src, edge_dst, edge_type, ne, n);
    node_nrel<<<(n + 255) / 256, 256>>>(n);

    // output typed linear (invnrel folded into t conversion)
    conv_split<<<(int)(((size_t)n * 128 + 255) / 256), 256>>>((const float*)p_t, (const float*)p_invnrel,
        (__nv_bfloat16*)p_thi, (__nv_bfloat16*)p_tlo, n);
    TcArgs a2;
    a2.Ahi = (const __nv_bfloat16*)p_thi;
    a2.Alo = (const __nv_bfloat16*)p_tlo;
    for (int m = 0; m < 3; m++) {
        a2.WhiT[m] = (const __nv_bfloat16*)p_whiT + (size_t)3 * TT * DD * DD;
        a2.WloT[m] = (const __nv_bfloat16*)p_wloT + (size_t)3 * TT * DD * DD;
        a2.bias[m] = ba;
        a2.out[m] = (float*)p_trans;
    }
    dim3 grid2((n + 127) / 128 + TT, DD / 128, 1);
    typed_gemm_tc<<<grid2, 256, 2 * STG_BUF>>>(a2);

    // gated residual + LN + passthrough
    finalize<<<(n + 7) / 8, 256>>>(x, skip, ln_g, ln_b, node_type, (float*)d_out, n);
}